// round 1
// baseline (speedup 1.0000x reference)
#include <cuda_runtime.h>
#include <math.h>

#define B_ 2
#define T_ 2048
#define E_ 2048
#define H_ 16
#define D_ 128
#define M_ (B_*T_)             // 4096
#define QKV_N (B_*H_*T_*D_)    // 8388608

// Scratch (static device allocations are the allowed form of scratch)
__device__ float g_Q[QKV_N];
__device__ float g_K[QKV_N];
__device__ float g_V[QKV_N];
__device__ float g_Y[QKV_N];     // attention out, [b, t, h*128+d] row-major [4096,2048]
__device__ float g_theta[64];    // RoPE thetas

// ---------------------------------------------------------------------------
// theta init: 64 values, computed in double then rounded to fp32 (correctly
// rounded theta; the subsequent fp32 multiply matches the reference's fp32 path)
// ---------------------------------------------------------------------------
__global__ void theta_init_kernel() {
    int j = threadIdx.x;
    if (j < 64) g_theta[j] = (float)pow(10000.0, -(double)j / 64.0);
}

// ---------------------------------------------------------------------------
// SGEMM core: one 128x128 output tile of  A[M,K] @ W[N,K]^T
// 256 threads, 8x8 per-thread micro-tile, BK=8, float4 everywhere.
// ---------------------------------------------------------------------------
__device__ __forceinline__ void gemm_core(
    const float* __restrict__ A, const float* __restrict__ W,
    int m0, int n0,
    float (&acc)[8][8],
    float (*As)[128], float (*Bs)[128])
{
    const int tid  = threadIdx.x;
    const int lrow = tid >> 1;           // 0..127
    const int lcol = (tid & 1) << 2;     // 0 or 4
    const int ty   = tid >> 4;           // 0..15
    const int tx   = tid & 15;           // 0..15
    const float* Aptr = A + (size_t)(m0 + lrow) * E_ + lcol;
    const float* Wptr = W + (size_t)(n0 + lrow) * E_ + lcol;

    for (int k0 = 0; k0 < E_; k0 += 8) {
        float4 av = *(const float4*)(Aptr + k0);
        float4 wv = *(const float4*)(Wptr + k0);
        As[lcol+0][lrow] = av.x; As[lcol+1][lrow] = av.y;
        As[lcol+2][lrow] = av.z; As[lcol+3][lrow] = av.w;
        Bs[lcol+0][lrow] = wv.x; Bs[lcol+1][lrow] = wv.y;
        Bs[lcol+2][lrow] = wv.z; Bs[lcol+3][lrow] = wv.w;
        __syncthreads();
        #pragma unroll
        for (int kk = 0; kk < 8; ++kk) {
            float4 a0 = *(const float4*)&As[kk][ty*8];
            float4 a1 = *(const float4*)&As[kk][ty*8+4];
            float4 b0 = *(const float4*)&Bs[kk][tx*8];
            float4 b1 = *(const float4*)&Bs[kk][tx*8+4];
            float ar[8] = {a0.x,a0.y,a0.z,a0.w,a1.x,a1.y,a1.z,a1.w};
            float br[8] = {b0.x,b0.y,b0.z,b0.w,b1.x,b1.y,b1.z,b1.w};
            #pragma unroll
            for (int i = 0; i < 8; ++i)
                #pragma unroll
                for (int j = 0; j < 8; ++j)
                    acc[i][j] = fmaf(ar[i], br[j], acc[i][j]);
        }
        __syncthreads();
    }
}

// ---------------------------------------------------------------------------
// QKV projection: grid (E/128=16, M/128=32, 3).  z selects Q/K/V.
// Epilogue scatters into [b,h,t,d] head-major layout (h == blockIdx.x since
// TILE_N == D == 128).
// ---------------------------------------------------------------------------
__global__ __launch_bounds__(256) void qkv_gemm_kernel(
    const float* __restrict__ X,
    const float* __restrict__ Wq, const float* __restrict__ bq,
    const float* __restrict__ Wk, const float* __restrict__ bk,
    const float* __restrict__ Wv, const float* __restrict__ bv)
{
    __shared__ float As[8][128];
    __shared__ float Bs[8][128];
    const float* W; const float* bias; float* dst;
    if (blockIdx.z == 0)      { W = Wq; bias = bq; dst = g_Q; }
    else if (blockIdx.z == 1) { W = Wk; bias = bk; dst = g_K; }
    else                      { W = Wv; bias = bv; dst = g_V; }

    const int m0 = blockIdx.y * 128;
    const int n0 = blockIdx.x * 128;
    float acc[8][8] = {};
    gemm_core(X, W, m0, n0, acc, As, Bs);

    const int ty = threadIdx.x >> 4, tx = threadIdx.x & 15;
    const int h = blockIdx.x;
    float bb[8];
    #pragma unroll
    for (int j = 0; j < 8; ++j) bb[j] = bias[n0 + tx*8 + j];

    #pragma unroll
    for (int i = 0; i < 8; ++i) {
        int m = m0 + ty*8 + i;
        int b = m >> 11, t = m & (T_-1);
        float* p = dst + (((size_t)(b*H_ + h))*T_ + t)*D_ + tx*8;
        float4 v0 = make_float4(acc[i][0]+bb[0], acc[i][1]+bb[1],
                                acc[i][2]+bb[2], acc[i][3]+bb[3]);
        float4 v1 = make_float4(acc[i][4]+bb[4], acc[i][5]+bb[5],
                                acc[i][6]+bb[6], acc[i][7]+bb[7]);
        *(float4*)p       = v0;
        *(float4*)(p + 4) = v1;
    }
}

// ---------------------------------------------------------------------------
// Output projection: g_Y [4096,2048] @ Wo^T + bo -> d_out
// ---------------------------------------------------------------------------
__global__ __launch_bounds__(256) void out_gemm_kernel(
    const float* __restrict__ Wo, const float* __restrict__ bo,
    float* __restrict__ out)
{
    __shared__ float As[8][128];
    __shared__ float Bs[8][128];
    const int m0 = blockIdx.y * 128;
    const int n0 = blockIdx.x * 128;
    float acc[8][8] = {};
    gemm_core(g_Y, Wo, m0, n0, acc, As, Bs);

    const int ty = threadIdx.x >> 4, tx = threadIdx.x & 15;
    float bb[8];
    #pragma unroll
    for (int j = 0; j < 8; ++j) bb[j] = bo[n0 + tx*8 + j];

    #pragma unroll
    for (int i = 0; i < 8; ++i) {
        int m = m0 + ty*8 + i;
        float* p = out + (size_t)m * E_ + n0 + tx*8;
        float4 v0 = make_float4(acc[i][0]+bb[0], acc[i][1]+bb[1],
                                acc[i][2]+bb[2], acc[i][3]+bb[3]);
        float4 v1 = make_float4(acc[i][4]+bb[4], acc[i][5]+bb[5],
                                acc[i][6]+bb[6], acc[i][7]+bb[7]);
        *(float4*)p       = v0;
        *(float4*)(p + 4) = v1;
    }
}

// ---------------------------------------------------------------------------
// RoPE in-place on g_Q / g_K (blockIdx.y selects).
// ang = fl32((t+1) * theta32): same fp32 multiply as the reference.
// ---------------------------------------------------------------------------
__global__ void rope_kernel() {
    const int total = B_*H_*T_*(D_/2);   // 4194304
    int idx = blockIdx.x * blockDim.x + threadIdx.x;
    if (idx >= total) return;
    int row = idx >> 6;           // [bh*T + t]
    int j   = idx & 63;
    int t   = row & (T_-1);
    float theta = g_theta[j];
    float ang = (float)(t + 1) * theta;
    float s, c;
    sincosf(ang, &s, &c);
    float* buf = (blockIdx.y == 0) ? g_Q : g_K;
    size_t base = (size_t)row * D_;
    float x0 = buf[base + j];
    float x1 = buf[base + j + 64];
    buf[base + j]      = x0*c - x1*s;
    buf[base + j + 64] = x1*c + x0*s;
}

// ---------------------------------------------------------------------------
// Flash attention, causal. grid (T/16, B*H), 128 threads.
// BQ=16 q rows per block, BKV=64; K and V time-share one smem buffer.
// Thread t owns O column d=t (16 registers).
// ---------------------------------------------------------------------------
__global__ __launch_bounds__(128) void attn_kernel() {
    __shared__ __align__(16) float Qs[16][132];
    __shared__ __align__(16) float KVs[64][132];
    __shared__ float Ss[16][68];
    __shared__ float m_s[16], l_s[16], alpha_s[16];

    const int tid = threadIdx.x;
    const int qt = blockIdx.x, bh = blockIdx.y;
    const int q0 = qt * 16;
    const float* Qp = g_Q + (size_t)bh * T_ * D_;
    const float* Kp = g_K + (size_t)bh * T_ * D_;
    const float* Vp = g_V + (size_t)bh * T_ * D_;

    // load Q tile (16 x 128)
    for (int i = tid; i < 16*32; i += 128) {
        int r = i >> 5, c4 = i & 31;
        *(float4*)&Qs[r][c4*4] = *(const float4*)(Qp + (size_t)(q0+r)*D_ + c4*4);
    }
    if (tid < 16) { m_s[tid] = -1e30f; l_s[tid] = 0.f; }

    float o[16];
    #pragma unroll
    for (int i = 0; i < 16; ++i) o[i] = 0.f;

    const int r  = tid >> 3;   // 0..15 (q row for S compute)
    const int cg = tid & 7;    // 0..7
    const float scale = 0.08838834764831845f;   // 1/sqrt(128)

    for (int k0 = 0; k0 < q0 + 16; k0 += 64) {
        __syncthreads();   // KVs free (prev PV done); first iter: Q load done
        // load K tile (64 x 128)
        for (int i = tid; i < 64*32; i += 128) {
            int rr = i >> 5, c4 = i & 31;
            *(float4*)&KVs[rr][c4*4] = *(const float4*)(Kp + (size_t)(k0+rr)*D_ + c4*4);
        }
        __syncthreads();

        // S = Q K^T : thread (r, cg) computes columns c = j*8+cg, j=0..7
        float sv[8];
        #pragma unroll
        for (int j = 0; j < 8; ++j) sv[j] = 0.f;
        #pragma unroll 4
        for (int k4 = 0; k4 < 32; ++k4) {
            float4 q4 = *(const float4*)&Qs[r][k4*4];
            #pragma unroll
            for (int j = 0; j < 8; ++j) {
                float4 kv = *(const float4*)&KVs[j*8+cg][k4*4];
                sv[j] += q4.x*kv.x + q4.y*kv.y + q4.z*kv.z + q4.w*kv.w;
            }
        }
        #pragma unroll
        for (int j = 0; j < 8; ++j) {
            int c = k0 + j*8 + cg;
            sv[j] = (c <= q0 + r) ? sv[j]*scale : -1e30f;
            Ss[r][j*8+cg] = sv[j];
        }
        __syncthreads();

        // row max + correction factor (16 threads)
        if (tid < 16) {
            float mo = m_s[tid], mx = mo;
            #pragma unroll 8
            for (int c = 0; c < 64; ++c) mx = fmaxf(mx, Ss[tid][c]);
            m_s[tid] = mx;
            alpha_s[tid] = __expf(mo - mx);
        }
        __syncthreads();

        // P = exp(S - m), l update, O rescale, V load (all in one phase)
        {
            float mx = m_s[r];
            float psum = 0.f;
            #pragma unroll
            for (int j = 0; j < 8; ++j) {
                float p = __expf(sv[j] - mx);
                Ss[r][j*8+cg] = p;
                psum += p;
            }
            #pragma unroll
            for (int off = 1; off < 8; off <<= 1)
                psum += __shfl_xor_sync(0xffffffffu, psum, off);
            if (cg == 0) l_s[r] = l_s[r]*alpha_s[r] + psum;
        }
        #pragma unroll
        for (int i = 0; i < 16; ++i) o[i] *= alpha_s[i];
        for (int i = tid; i < 64*32; i += 128) {
            int rr = i >> 5, c4 = i & 31;
            *(float4*)&KVs[rr][c4*4] = *(const float4*)(Vp + (size_t)(k0+rr)*D_ + c4*4);
        }
        __syncthreads();

        // O += P V : thread owns column d = tid
        #pragma unroll 4
        for (int c = 0; c < 64; ++c) {
            float vv = KVs[c][tid];
            #pragma unroll
            for (int i = 0; i < 16; ++i) o[i] = fmaf(Ss[i][c], vv, o[i]);
        }
    }

    // epilogue: normalize and write to g_Y in [b, t, h*128+d] layout
    const int b = bh >> 4, h = bh & 15;
    #pragma unroll
    for (int i = 0; i < 16; ++i) {
        float inv = 1.0f / l_s[i];
        g_Y[((size_t)(b*T_ + q0 + i))*E_ + h*D_ + tid] = o[i] * inv;
    }
}

// ---------------------------------------------------------------------------
extern "C" void kernel_launch(void* const* d_in, const int* in_sizes, int n_in,
                              void* d_out, int out_size) {
    const float* x  = (const float*)d_in[0];
    const float* Wq = (const float*)d_in[1];
    const float* bq = (const float*)d_in[2];
    const float* Wk = (const float*)d_in[3];
    const float* bk = (const float*)d_in[4];
    const float* Wv = (const float*)d_in[5];
    const float* bv = (const float*)d_in[6];
    const float* Wo = (const float*)d_in[7];
    const float* bo = (const float*)d_in[8];
    float* out = (float*)d_out;

    theta_init_kernel<<<1, 64>>>();

    dim3 g1(E_/128, M_/128, 3);
    qkv_gemm_kernel<<<g1, 256>>>(x, Wq, bq, Wk, bk, Wv, bv);

    const int rope_total = B_*H_*T_*(D_/2);
    dim3 g2((rope_total + 255)/256, 2);
    rope_kernel<<<g2, 256>>>();

    dim3 g3(T_/16, B_*H_);
    attn_kernel<<<g3, 128>>>();

    dim3 g4(E_/128, M_/128);
    out_gemm_kernel<<<g4, 256>>>(Wo, bo, out);
}

// round 4
// speedup vs baseline: 3.2262x; 3.2262x over previous
#include <cuda_runtime.h>
#include <cuda_fp16.h>
#include <math.h>
#include <cstdint>

#define B_ 2
#define T_ 2048
#define E_ 2048
#define H_ 16
#define D_ 128
#define M_ (B_*T_)             // 4096
#define QKV_N (B_*H_*T_*D_)    // 8388608
#define WN_ (E_*E_)            // 4194304
#define QSCALE 0.08838834764831845f   // 1/sqrt(128)

// ---------------- scratch ----------------------------------------------------
__device__ float  g_Q[QKV_N];          // fp32 Q (pre-rope), head-major [b,h,t,d]
__device__ float  g_K[QKV_N];
__device__ __half g_Qh[QKV_N]; __device__ __half g_Ql[QKV_N];   // post-rope, scaled, split
__device__ __half g_Kh[QKV_N]; __device__ __half g_Kl[QKV_N];
__device__ __half g_Vh[QKV_N]; __device__ __half g_Vl[QKV_N];
__device__ __half g_Yh[QKV_N]; __device__ __half g_Yl[QKV_N];   // attn out [b,t,h*128+d]
__device__ __half g_Xh[M_*E_]; __device__ __half g_Xl[M_*E_];
__device__ __half g_Wh[4*WN_]; __device__ __half g_Wl[4*WN_];
__device__ float  g_theta[64];

// ---------------- helpers ----------------------------------------------------
__device__ __forceinline__ uint32_t smem_u32(const void* p) {
    uint32_t a;
    asm("{ .reg .u64 t; cvta.to.shared.u64 t, %1; cvt.u32.u64 %0, t; }" : "=r"(a) : "l"(p));
    return a;
}
__device__ __forceinline__ void cp16(uint32_t d, const void* g) {
    asm volatile("cp.async.cg.shared.global [%0], [%1], 16;" :: "r"(d), "l"(g));
}
__device__ __forceinline__ void ldsm4(uint32_t (&r)[4], uint32_t addr) {
    asm volatile("ldmatrix.sync.aligned.m8n8.x4.shared.b16 {%0,%1,%2,%3}, [%4];"
        : "=r"(r[0]), "=r"(r[1]), "=r"(r[2]), "=r"(r[3]) : "r"(addr));
}
__device__ __forceinline__ void ldsm4t(uint32_t (&r)[4], uint32_t addr) {
    asm volatile("ldmatrix.sync.aligned.m8n8.x4.trans.shared.b16 {%0,%1,%2,%3}, [%4];"
        : "=r"(r[0]), "=r"(r[1]), "=r"(r[2]), "=r"(r[3]) : "r"(addr));
}
__device__ __forceinline__ void mma16816(float (&d)[4], const uint32_t (&a)[4],
                                         uint32_t b0, uint32_t b1) {
    asm volatile("mma.sync.aligned.m16n8k16.row.col.f32.f16.f16.f32 "
        "{%0,%1,%2,%3},{%4,%5,%6,%7},{%8,%9},{%0,%1,%2,%3};"
        : "+f"(d[0]), "+f"(d[1]), "+f"(d[2]), "+f"(d[3])
        : "r"(a[0]), "r"(a[1]), "r"(a[2]), "r"(a[3]), "r"(b0), "r"(b1));
}
__device__ __forceinline__ void split2(float x0, float x1, uint32_t& hi, uint32_t& lo) {
    __half2 h = __floats2half2_rn(x0, x1);
    float2 b = __half22float2(h);
    __half2 l = __floats2half2_rn(x0 - b.x, x1 - b.y);
    hi = *(uint32_t*)&h; lo = *(uint32_t*)&l;
}
__device__ __forceinline__ float qmax(float v) {
    v = fmaxf(v, __shfl_xor_sync(0xffffffffu, v, 1));
    v = fmaxf(v, __shfl_xor_sync(0xffffffffu, v, 2));
    return v;
}
__device__ __forceinline__ float qsum(float v) {
    v += __shfl_xor_sync(0xffffffffu, v, 1);
    v += __shfl_xor_sync(0xffffffffu, v, 2);
    return v;
}

// ---------------------------------------------------------------------------
__global__ void theta_init_kernel() {
    int j = threadIdx.x;
    if (j < 64) g_theta[j] = (float)pow(10000.0, -(double)j / 64.0);
}

// f32 -> (hi, lo) f16 split, 4 elems/thread
__global__ void split_kernel(const float* __restrict__ src,
                             __half* __restrict__ hi, __half* __restrict__ lo, int n4) {
    int i = blockIdx.x * blockDim.x + threadIdx.x;
    if (i >= n4) return;
    float4 v = ((const float4*)src)[i];
    uint32_t h0, l0, h1, l1;
    split2(v.x, v.y, h0, l0);
    split2(v.z, v.w, h1, l1);
    uint32_t* H = (uint32_t*)hi + (size_t)i * 2;
    uint32_t* L = (uint32_t*)lo + (size_t)i * 2;
    H[0] = h0; H[1] = h1; L[0] = l0; L[1] = l1;
}

// ---------------------------------------------------------------------------
// GEMM: C[M,N] = A[M,K] @ W[N,K]^T + bias  via 3-pass split-f16 HMMA
// BM=BN=128, BK=64, 256 thr (8 warps, 2x4), 2-stage cp.async pipeline.
// mode 0: ->g_Q fp32 head-major   mode 1: ->g_K fp32 head-major
// mode 2: ->g_Vh/g_Vl split head-major      mode 3: ->outF fp32 row-major
// ---------------------------------------------------------------------------
#define MAT_B  (128*144)        // bytes per matrix per stage (128 rows x 144B pitch)
#define STAGE_B (4*MAT_B)       // Ah, Al, Wh, Wl
#define GEMM_SMEM (2*STAGE_B)   // 147456

__device__ __forceinline__ void gemm_load_stage(
    uint32_t sb, const __half* Ah, const __half* Al,
    const __half* Bh, const __half* Bl, int m0, int n0, int k0, int tid)
{
    const __half* srcs[4] = { Ah, Al, Bh, Bl };
    #pragma unroll
    for (int mat = 0; mat < 4; ++mat) {
        int rbase = (mat < 2) ? m0 : n0;
        #pragma unroll
        for (int p = 0; p < 4; ++p) {
            int idx = tid + p * 256;
            int row = idx >> 3, c16 = idx & 7;
            const __half* g = srcs[mat] + (size_t)(rbase + row) * E_ + k0 + c16 * 8;
            cp16(sb + mat * MAT_B + row * 144 + c16 * 16, g);
        }
    }
    asm volatile("cp.async.commit_group;" ::: "memory");
}

__global__ __launch_bounds__(256) void gemm_tc(
    const __half* __restrict__ Ah, const __half* __restrict__ Al,
    const __half* __restrict__ Bh, const __half* __restrict__ Bl,
    const float* __restrict__ bias, float* __restrict__ outF, int mode)
{
    extern __shared__ __align__(16) char dsmem[];
    const uint32_t sbase = smem_u32(dsmem);
    const int tid = threadIdx.x;
    const int lane = tid & 31;
    const int wid = tid >> 5;
    const int wm = wid >> 2, wn = wid & 3;
    const int n0 = blockIdx.x * 128;
    const int m0 = blockIdx.y * 128;

    float acc[4][4][4] = {};

    gemm_load_stage(sbase,           Ah, Al, Bh, Bl, m0, n0, 0,  tid);
    gemm_load_stage(sbase + STAGE_B, Ah, Al, Bh, Bl, m0, n0, 64, tid);

    for (int i = 0; i < E_/64; ++i) {
        const uint32_t sb = sbase + (i & 1) * STAGE_B;
        asm volatile("cp.async.wait_group 1;" ::: "memory");
        __syncthreads();

        #pragma unroll
        for (int k16 = 0; k16 < 4; ++k16) {
            uint32_t ah[4][4], al[4][4];
            #pragma unroll
            for (int mf = 0; mf < 4; ++mf) {
                uint32_t addr = sb + (wm*64 + mf*16 + (lane & 15)) * 144
                              + k16*32 + (lane >> 4) * 16;
                ldsm4(ah[mf], addr);
                ldsm4(al[mf], addr + MAT_B);
            }
            uint32_t bh[2][4], bl[2][4];
            #pragma unroll
            for (int g = 0; g < 2; ++g) {
                uint32_t addr = sb + 2*MAT_B
                              + (wn*32 + g*16 + (lane & 7) + ((lane >> 4) & 1) * 8) * 144
                              + k16*32 + ((lane >> 3) & 1) * 16;
                ldsm4(bh[g], addr);
                ldsm4(bl[g], addr + MAT_B);
            }
            #pragma unroll
            for (int mf = 0; mf < 4; ++mf)
                #pragma unroll
                for (int nf = 0; nf < 4; ++nf) {
                    int g = nf >> 1, h = (nf & 1) * 2;
                    mma16816(acc[mf][nf], ah[mf], bh[g][h], bh[g][h+1]);
                    mma16816(acc[mf][nf], ah[mf], bl[g][h], bl[g][h+1]);
                    mma16816(acc[mf][nf], al[mf], bh[g][h], bh[g][h+1]);
                }
        }
        __syncthreads();
        if (i + 2 < E_/64)
            gemm_load_stage(sb, Ah, Al, Bh, Bl, m0, n0, (i + 2) * 64, tid);
        else
            asm volatile("cp.async.commit_group;" ::: "memory");
    }

    // epilogue
    #pragma unroll
    for (int nf = 0; nf < 4; ++nf) {
        int d = wn*32 + nf*8 + (lane & 3) * 2;          // 0..127 within tile
        int gcol = n0 + d;
        float b0 = bias[gcol], b1 = bias[gcol + 1];
        #pragma unroll
        for (int mf = 0; mf < 4; ++mf) {
            int row0 = m0 + wm*64 + mf*16 + (lane >> 2);
            #pragma unroll
            for (int half = 0; half < 2; ++half) {
                int row = row0 + half * 8;
                float v0 = acc[mf][nf][half*2 + 0] + b0;
                float v1 = acc[mf][nf][half*2 + 1] + b1;
                if (mode == 3) {
                    *(float2*)(outF + (size_t)row * E_ + gcol) = make_float2(v0, v1);
                } else {
                    int b = row >> 11, t = row & (T_ - 1), h = blockIdx.x;
                    size_t idx = (((size_t)(b*H_ + h)) * T_ + t) * D_ + d;
                    if (mode == 2) {
                        uint32_t hi, lo;
                        split2(v0, v1, hi, lo);
                        *(uint32_t*)&g_Vh[idx] = hi;
                        *(uint32_t*)&g_Vl[idx] = lo;
                    } else {
                        float* dst = (mode == 0) ? g_Q : g_K;
                        *(float2*)(dst + idx) = make_float2(v0, v1);
                    }
                }
            }
        }
    }
}

// ---------------------------------------------------------------------------
// RoPE + scale (Q only) + hi/lo split.  y-dim: 0 = Q, 1 = K.
// ---------------------------------------------------------------------------
__global__ void rope_split_kernel() {
    const int total = B_*H_*T_*(D_/2);
    int idx = blockIdx.x * blockDim.x + threadIdx.x;
    if (idx >= total) return;
    int row = idx >> 6;
    int j   = idx & 63;
    int t   = row & (T_ - 1);
    float ang = (float)(t + 1) * g_theta[j];
    float s, c;
    sincosf(ang, &s, &c);
    int isK = blockIdx.y;
    const float* src = isK ? g_K : g_Q;
    __half* dh = isK ? g_Kh : g_Qh;
    __half* dl = isK ? g_Kl : g_Ql;
    size_t base = (size_t)row * D_;
    float x0 = src[base + j];
    float x1 = src[base + j + 64];
    float r0 = x0*c - x1*s;
    float r1 = x1*c + x0*s;
    if (!isK) { r0 *= QSCALE; r1 *= QSCALE; }
    __half h0 = __float2half_rn(r0);
    __half h1 = __float2half_rn(r1);
    dh[base + j]      = h0;
    dh[base + j + 64] = h1;
    dl[base + j]      = __float2half_rn(r0 - __half2float(h0));
    dl[base + j + 64] = __float2half_rn(r1 - __half2float(h1));
}

// ---------------------------------------------------------------------------
// Flash attention, causal, split-f16 HMMA, fp32 softmax.
// grid (T/64, B*H), 128 threads (4 warps). BQ=64 (16 rows/warp), BKV=64.
// K and V time-share one hi/lo smem buffer.
// ---------------------------------------------------------------------------
#define AT_ROW 136                       // halves per smem row (128 + 8 pad)
#define AT_TILE (64*AT_ROW)              // halves per matrix
#define ATTN_SMEM (4*AT_TILE*2)          // Qh,Ql,KVh,KVl = 69632 B

__global__ __launch_bounds__(128) void attn_tc() {
    extern __shared__ __align__(16) __half asmem[];
    __half* sQh = asmem;
    __half* sQl = asmem + AT_TILE;
    __half* sKh = asmem + 2*AT_TILE;
    __half* sKl = asmem + 3*AT_TILE;
    const uint32_t uQh = smem_u32(sQh), uQl = smem_u32(sQl);
    const uint32_t uKh = smem_u32(sKh), uKl = smem_u32(sKl);

    const int tid = threadIdx.x;
    const int lane = tid & 31;
    const int w = tid >> 5;
    const int q0 = blockIdx.x * 64;
    const int bh = blockIdx.y;
    const __half* Qhp = g_Qh + (size_t)bh * T_ * D_;
    const __half* Qlp = g_Ql + (size_t)bh * T_ * D_;
    const __half* Khp = g_Kh + (size_t)bh * T_ * D_;
    const __half* Klp = g_Kl + (size_t)bh * T_ * D_;
    const __half* Vhp = g_Vh + (size_t)bh * T_ * D_;
    const __half* Vlp = g_Vl + (size_t)bh * T_ * D_;

    // load Q tile (hi + lo)
    #pragma unroll
    for (int p = 0; p < 8; ++p) {
        int idx = tid + p * 128;
        int row = idx >> 4, c8 = idx & 15;
        *(float4*)&sQh[row*AT_ROW + c8*8] = *(const float4*)&Qhp[(size_t)(q0+row)*D_ + c8*8];
        *(float4*)&sQl[row*AT_ROW + c8*8] = *(const float4*)&Qlp[(size_t)(q0+row)*D_ + c8*8];
    }

    float of[16][4] = {};
    float m0 = -1e30f, m1 = -1e30f, l0 = 0.f, l1 = 0.f;
    const int nblocks = q0/64 + 1;

    for (int it = 0; it < nblocks; ++it) {
        const int k0 = it * 64;
        const bool diag = (it == nblocks - 1);

        __syncthreads();   // prev V reads done (or Q load done on it=0)
        #pragma unroll
        for (int p = 0; p < 8; ++p) {
            int idx = tid + p * 128;
            int row = idx >> 4, c8 = idx & 15;
            *(float4*)&sKh[row*AT_ROW + c8*8] = *(const float4*)&Khp[(size_t)(k0+row)*D_ + c8*8];
            *(float4*)&sKl[row*AT_ROW + c8*8] = *(const float4*)&Klp[(size_t)(k0+row)*D_ + c8*8];
        }
        __syncthreads();

        // ---- S = Q K^T (3-pass split) ----
        float sf[8][4] = {};
        #pragma unroll
        for (int k16 = 0; k16 < 8; ++k16) {
            uint32_t aqh[4], aql[4];
            uint32_t aaddr = (w*16 + (lane & 15)) * (AT_ROW*2) + k16*32 + (lane >> 4) * 16;
            ldsm4(aqh, uQh + aaddr);
            ldsm4(aql, uQl + aaddr);
            #pragma unroll
            for (int g = 0; g < 4; ++g) {
                uint32_t kbh[4], kbl[4];
                uint32_t baddr = (g*16 + (lane & 7) + ((lane >> 4) & 1) * 8) * (AT_ROW*2)
                               + k16*32 + ((lane >> 3) & 1) * 16;
                ldsm4(kbh, uKh + baddr);
                ldsm4(kbl, uKl + baddr);
                mma16816(sf[2*g],   aqh, kbh[0], kbh[1]);
                mma16816(sf[2*g],   aqh, kbl[0], kbl[1]);
                mma16816(sf[2*g],   aql, kbh[0], kbh[1]);
                mma16816(sf[2*g+1], aqh, kbh[2], kbh[3]);
                mma16816(sf[2*g+1], aqh, kbl[2], kbl[3]);
                mma16816(sf[2*g+1], aql, kbh[2], kbh[3]);
            }
        }

        // ---- mask (diagonal block only) ----
        const int rg0 = q0 + w*16 + (lane >> 2);
        if (diag) {
            #pragma unroll
            for (int n = 0; n < 8; ++n) {
                int col = k0 + n*8 + (lane & 3) * 2;
                if (col     > rg0)     sf[n][0] = -1e30f;
                if (col + 1 > rg0)     sf[n][1] = -1e30f;
                if (col     > rg0 + 8) sf[n][2] = -1e30f;
                if (col + 1 > rg0 + 8) sf[n][3] = -1e30f;
            }
        }

        // ---- online softmax ----
        float mx0 = -1e30f, mx1 = -1e30f;
        #pragma unroll
        for (int n = 0; n < 8; ++n) {
            mx0 = fmaxf(mx0, fmaxf(sf[n][0], sf[n][1]));
            mx1 = fmaxf(mx1, fmaxf(sf[n][2], sf[n][3]));
        }
        mx0 = qmax(mx0); mx1 = qmax(mx1);
        float mn0 = fmaxf(m0, mx0), mn1 = fmaxf(m1, mx1);
        float a0 = __expf(m0 - mn0), a1 = __expf(m1 - mn1);
        m0 = mn0; m1 = mn1;

        uint32_t pa[4][4], pal[4][4];
        float s0 = 0.f, s1 = 0.f;
        #pragma unroll
        for (int n = 0; n < 8; ++n) {
            float p0 = __expf(sf[n][0] - mn0);
            float p1 = __expf(sf[n][1] - mn0);
            float p2 = __expf(sf[n][2] - mn1);
            float p3 = __expf(sf[n][3] - mn1);
            s0 += p0 + p1; s1 += p2 + p3;
            int kt = n >> 1, o = (n & 1) * 2;
            split2(p0, p1, pa[kt][o + 0], pal[kt][o + 0]);
            split2(p2, p3, pa[kt][o + 1], pal[kt][o + 1]);
        }
        s0 = qsum(s0); s1 = qsum(s1);
        l0 = l0 * a0 + s0;
        l1 = l1 * a1 + s1;
        #pragma unroll
        for (int n = 0; n < 16; ++n) {
            of[n][0] *= a0; of[n][1] *= a0;
            of[n][2] *= a1; of[n][3] *= a1;
        }

        // ---- load V into the K buffers ----
        __syncthreads();
        #pragma unroll
        for (int p = 0; p < 8; ++p) {
            int idx = tid + p * 128;
            int row = idx >> 4, c8 = idx & 15;
            *(float4*)&sKh[row*AT_ROW + c8*8] = *(const float4*)&Vhp[(size_t)(k0+row)*D_ + c8*8];
            *(float4*)&sKl[row*AT_ROW + c8*8] = *(const float4*)&Vlp[(size_t)(k0+row)*D_ + c8*8];
        }
        __syncthreads();

        // ---- O += P V (3-pass split) ----
        #pragma unroll
        for (int kt = 0; kt < 4; ++kt) {
            #pragma unroll
            for (int g = 0; g < 8; ++g) {
                uint32_t vbh[4], vbl[4];
                uint32_t vaddr = (kt*16 + (lane & 7) + ((lane >> 3) & 1) * 8) * (AT_ROW*2)
                               + g*32 + ((lane >> 4) & 1) * 16;
                ldsm4t(vbh, uKh + vaddr);
                ldsm4t(vbl, uKl + vaddr);
                mma16816(of[2*g],   pa[kt],  vbh[0], vbh[1]);
                mma16816(of[2*g],   pa[kt],  vbl[0], vbl[1]);
                mma16816(of[2*g],   pal[kt], vbh[0], vbh[1]);
                mma16816(of[2*g+1], pa[kt],  vbh[2], vbh[3]);
                mma16816(of[2*g+1], pa[kt],  vbl[2], vbl[3]);
                mma16816(of[2*g+1], pal[kt], vbh[2], vbh[3]);
            }
        }
    }

    // ---- epilogue: normalize, split, store ----
    float inv0 = 1.0f / l0, inv1 = 1.0f / l1;
    const int b = bh >> 4, h = bh & 15;
    const int row0 = q0 + w*16 + (lane >> 2);
    size_t base0 = ((size_t)(b*T_ + row0)) * E_ + h*D_;
    size_t base1 = base0 + 8 * E_;
    #pragma unroll
    for (int n = 0; n < 16; ++n) {
        int col = n*8 + (lane & 3) * 2;
        uint32_t hi, lo;
        split2(of[n][0] * inv0, of[n][1] * inv0, hi, lo);
        *(uint32_t*)&g_Yh[base0 + col] = hi;
        *(uint32_t*)&g_Yl[base0 + col] = lo;
        split2(of[n][2] * inv1, of[n][3] * inv1, hi, lo);
        *(uint32_t*)&g_Yh[base1 + col] = hi;
        *(uint32_t*)&g_Yl[base1 + col] = lo;
    }
}

// ---------------------------------------------------------------------------
extern "C" void kernel_launch(void* const* d_in, const int* in_sizes, int n_in,
                              void* d_out, int out_size) {
    const float* x  = (const float*)d_in[0];
    const float* Wq = (const float*)d_in[1];
    const float* bq = (const float*)d_in[2];
    const float* Wk = (const float*)d_in[3];
    const float* bk = (const float*)d_in[4];
    const float* Wv = (const float*)d_in[5];
    const float* bv = (const float*)d_in[6];
    const float* Wo = (const float*)d_in[7];
    const float* bo = (const float*)d_in[8];
    float* out = (float*)d_out;

    cudaFuncSetAttribute(gemm_tc, cudaFuncAttributeMaxDynamicSharedMemorySize, GEMM_SMEM);
    cudaFuncSetAttribute(attn_tc, cudaFuncAttributeMaxDynamicSharedMemorySize, ATTN_SMEM);

    theta_init_kernel<<<1, 64>>>();

    __half *Xh, *Xl, *Wh, *Wl, *Yh, *Yl;
    cudaGetSymbolAddress((void**)&Xh, g_Xh);
    cudaGetSymbolAddress((void**)&Xl, g_Xl);
    cudaGetSymbolAddress((void**)&Wh, g_Wh);
    cudaGetSymbolAddress((void**)&Wl, g_Wl);
    cudaGetSymbolAddress((void**)&Yh, g_Yh);
    cudaGetSymbolAddress((void**)&Yl, g_Yl);

    split_kernel<<<(M_*E_/4 + 255)/256, 256>>>(x, Xh, Xl, M_*E_/4);
    split_kernel<<<(WN_/4 + 255)/256, 256>>>(Wq, Wh + 0*(size_t)WN_, Wl + 0*(size_t)WN_, WN_/4);
    split_kernel<<<(WN_/4 + 255)/256, 256>>>(Wk, Wh + 1*(size_t)WN_, Wl + 1*(size_t)WN_, WN_/4);
    split_kernel<<<(WN_/4 + 255)/256, 256>>>(Wv, Wh + 2*(size_t)WN_, Wl + 2*(size_t)WN_, WN_/4);
    split_kernel<<<(WN_/4 + 255)/256, 256>>>(Wo, Wh + 3*(size_t)WN_, Wl + 3*(size_t)WN_, WN_/4);

    dim3 gg(E_/128, M_/128);
    gemm_tc<<<gg, 256, GEMM_SMEM>>>(Xh, Xl, Wh + 0*(size_t)WN_, Wl + 0*(size_t)WN_, bq, nullptr, 0);
    gemm_tc<<<gg, 256, GEMM_SMEM>>>(Xh, Xl, Wh + 1*(size_t)WN_, Wl + 1*(size_t)WN_, bk, nullptr, 1);
    gemm_tc<<<gg, 256, GEMM_SMEM>>>(Xh, Xl, Wh + 2*(size_t)WN_, Wl + 2*(size_t)WN_, bv, nullptr, 2);

    const int rope_total = B_*H_*T_*(D_/2);
    dim3 g2((rope_total + 255)/256, 2);
    rope_split_kernel<<<g2, 256>>>();

    dim3 g3(T_/64, B_*H_);
    attn_tc<<<g3, 128, ATTN_SMEM>>>();

    gemm_tc<<<gg, 256, GEMM_SMEM>>>(Yh, Yl, Wh + 3*(size_t)WN_, Wl + 3*(size_t)WN_, bo, out, 3);
}

// round 5
// speedup vs baseline: 4.8070x; 1.4900x over previous
#include <cuda_runtime.h>
#include <cuda_fp16.h>
#include <math.h>
#include <cstdint>

#define B_ 2
#define T_ 2048
#define E_ 2048
#define H_ 16
#define D_ 128
#define M_ (B_*T_)             // 4096
#define QKV_N (B_*H_*T_*D_)    // 8388608
#define WN_ (E_*E_)            // 4194304
#define QSCALE 0.08838834764831845f   // 1/sqrt(128)

// ---------------- scratch ----------------------------------------------------
__device__ float  g_Q[QKV_N];          // fp32 Q (pre-rope), head-major [b,h,t,d]
__device__ float  g_K[QKV_N];
__device__ __half g_Qh[QKV_N];                                  // post-rope, scaled, f16
__device__ __half g_Kh[QKV_N]; __device__ __half g_Kl[QKV_N];   // post-rope, split
__device__ __half g_Vh[QKV_N]; __device__ __half g_Vl[QKV_N];
__device__ __half g_Yh[QKV_N];                                  // attn out [b,t,h*128+d]
__device__ __half g_Xh[M_*E_];
__device__ __half g_Wh[4*WN_]; __device__ __half g_Wl[4*WN_];
__device__ float  g_theta[64];

// ---------------- helpers ----------------------------------------------------
__device__ __forceinline__ uint32_t smem_u32(const void* p) {
    uint32_t a;
    asm("{ .reg .u64 t; cvta.to.shared.u64 t, %1; cvt.u32.u64 %0, t; }" : "=r"(a) : "l"(p));
    return a;
}
__device__ __forceinline__ void cp16(uint32_t d, const void* g) {
    asm volatile("cp.async.cg.shared.global [%0], [%1], 16;" :: "r"(d), "l"(g));
}
__device__ __forceinline__ void ldsm4(uint32_t (&r)[4], uint32_t addr) {
    asm volatile("ldmatrix.sync.aligned.m8n8.x4.shared.b16 {%0,%1,%2,%3}, [%4];"
        : "=r"(r[0]), "=r"(r[1]), "=r"(r[2]), "=r"(r[3]) : "r"(addr));
}
__device__ __forceinline__ void ldsm4t(uint32_t (&r)[4], uint32_t addr) {
    asm volatile("ldmatrix.sync.aligned.m8n8.x4.trans.shared.b16 {%0,%1,%2,%3}, [%4];"
        : "=r"(r[0]), "=r"(r[1]), "=r"(r[2]), "=r"(r[3]) : "r"(addr));
}
__device__ __forceinline__ void mma16816(float (&d)[4], const uint32_t (&a)[4],
                                         uint32_t b0, uint32_t b1) {
    asm volatile("mma.sync.aligned.m16n8k16.row.col.f32.f16.f16.f32 "
        "{%0,%1,%2,%3},{%4,%5,%6,%7},{%8,%9},{%0,%1,%2,%3};"
        : "+f"(d[0]), "+f"(d[1]), "+f"(d[2]), "+f"(d[3])
        : "r"(a[0]), "r"(a[1]), "r"(a[2]), "r"(a[3]), "r"(b0), "r"(b1));
}
__device__ __forceinline__ void split2(float x0, float x1, uint32_t& hi, uint32_t& lo) {
    __half2 h = __floats2half2_rn(x0, x1);
    float2 b = __half22float2(h);
    __half2 l = __floats2half2_rn(x0 - b.x, x1 - b.y);
    hi = *(uint32_t*)&h; lo = *(uint32_t*)&l;
}
__device__ __forceinline__ uint32_t pack2(float x0, float x1) {
    __half2 h = __floats2half2_rn(x0, x1);
    return *(uint32_t*)&h;
}
__device__ __forceinline__ float qmax(float v) {
    v = fmaxf(v, __shfl_xor_sync(0xffffffffu, v, 1));
    v = fmaxf(v, __shfl_xor_sync(0xffffffffu, v, 2));
    return v;
}
__device__ __forceinline__ float qsum(float v) {
    v += __shfl_xor_sync(0xffffffffu, v, 1);
    v += __shfl_xor_sync(0xffffffffu, v, 2);
    return v;
}

// ---------------------------------------------------------------------------
__global__ void theta_init_kernel() {
    int j = threadIdx.x;
    if (j < 64) g_theta[j] = (float)pow(10000.0, -(double)j / 64.0);
}

// f32 -> f16 (hi only)
__global__ void f2h_kernel(const float* __restrict__ src, __half* __restrict__ dst, int n4) {
    int i = blockIdx.x * blockDim.x + threadIdx.x;
    if (i < n4) {
        float4 v = ((const float4*)src)[i];
        uint32_t* d = (uint32_t*)dst + (size_t)i * 2;
        d[0] = pack2(v.x, v.y);
        d[1] = pack2(v.z, v.w);
    }
}

// f32 -> (hi, lo) f16 split (weights only)
__global__ void split_kernel(const float* __restrict__ src,
                             __half* __restrict__ hi, __half* __restrict__ lo, int n4) {
    int i = blockIdx.x * blockDim.x + threadIdx.x;
    if (i >= n4) return;
    float4 v = ((const float4*)src)[i];
    uint32_t h0, l0, h1, l1;
    split2(v.x, v.y, h0, l0);
    split2(v.z, v.w, h1, l1);
    uint32_t* H = (uint32_t*)hi + (size_t)i * 2;
    uint32_t* L = (uint32_t*)lo + (size_t)i * 2;
    H[0] = h0; H[1] = h1; L[0] = l0; L[1] = l1;
}

// ---------------------------------------------------------------------------
// GEMM: C[M,N] = A_hi[M,K] @ (W_hi + W_lo)[N,K]^T + bias  (2-pass HMMA)
// BM=BN=128, BK=64, 256 thr (8 warps, 2x4), 2-stage cp.async pipeline.
// mode 0: ->g_Q fp32 head-major   mode 1: ->g_K fp32 head-major
// mode 2: ->g_Vh/g_Vl split head-major      mode 3: ->outF fp32 row-major
// ---------------------------------------------------------------------------
#define MAT_B  (128*144)        // bytes per matrix per stage (128 rows x 144B pitch)
#define STAGE_B (3*MAT_B)       // Ah, Wh, Wl
#define GEMM_SMEM (2*STAGE_B)   // 110592

__device__ __forceinline__ void gemm_load_stage(
    uint32_t sb, const __half* Ah, const __half* Bh, const __half* Bl,
    int m0, int n0, int k0, int tid)
{
    const __half* srcs[3] = { Ah, Bh, Bl };
    #pragma unroll
    for (int mat = 0; mat < 3; ++mat) {
        int rbase = (mat == 0) ? m0 : n0;
        #pragma unroll
        for (int p = 0; p < 4; ++p) {
            int idx = tid + p * 256;
            int row = idx >> 3, c16 = idx & 7;
            const __half* g = srcs[mat] + (size_t)(rbase + row) * E_ + k0 + c16 * 8;
            cp16(sb + mat * MAT_B + row * 144 + c16 * 16, g);
        }
    }
    asm volatile("cp.async.commit_group;" ::: "memory");
}

__global__ __launch_bounds__(256) void gemm_tc(
    const __half* __restrict__ Ah,
    const __half* __restrict__ Bh, const __half* __restrict__ Bl,
    const float* __restrict__ bias, float* __restrict__ outF, int mode)
{
    extern __shared__ __align__(16) char dsmem[];
    const uint32_t sbase = smem_u32(dsmem);
    const int tid = threadIdx.x;
    const int lane = tid & 31;
    const int wid = tid >> 5;
    const int wm = wid >> 2, wn = wid & 3;
    const int n0 = blockIdx.x * 128;
    const int m0 = blockIdx.y * 128;

    float acc[4][4][4] = {};

    gemm_load_stage(sbase,           Ah, Bh, Bl, m0, n0, 0,  tid);
    gemm_load_stage(sbase + STAGE_B, Ah, Bh, Bl, m0, n0, 64, tid);

    for (int i = 0; i < E_/64; ++i) {
        const uint32_t sb = sbase + (i & 1) * STAGE_B;
        asm volatile("cp.async.wait_group 1;" ::: "memory");
        __syncthreads();

        #pragma unroll
        for (int k16 = 0; k16 < 4; ++k16) {
            uint32_t ah[4][4];
            #pragma unroll
            for (int mf = 0; mf < 4; ++mf) {
                uint32_t addr = sb + (wm*64 + mf*16 + (lane & 15)) * 144
                              + k16*32 + (lane >> 4) * 16;
                ldsm4(ah[mf], addr);
            }
            uint32_t bh[2][4], bl[2][4];
            #pragma unroll
            for (int g = 0; g < 2; ++g) {
                uint32_t addr = sb + MAT_B
                              + (wn*32 + g*16 + (lane & 7) + ((lane >> 4) & 1) * 8) * 144
                              + k16*32 + ((lane >> 3) & 1) * 16;
                ldsm4(bh[g], addr);
                ldsm4(bl[g], addr + MAT_B);
            }
            #pragma unroll
            for (int mf = 0; mf < 4; ++mf)
                #pragma unroll
                for (int nf = 0; nf < 4; ++nf) {
                    int g = nf >> 1, h = (nf & 1) * 2;
                    mma16816(acc[mf][nf], ah[mf], bh[g][h], bh[g][h+1]);
                    mma16816(acc[mf][nf], ah[mf], bl[g][h], bl[g][h+1]);
                }
        }
        __syncthreads();
        if (i + 2 < E_/64)
            gemm_load_stage(sb, Ah, Bh, Bl, m0, n0, (i + 2) * 64, tid);
        else
            asm volatile("cp.async.commit_group;" ::: "memory");
    }

    // epilogue
    #pragma unroll
    for (int nf = 0; nf < 4; ++nf) {
        int d = wn*32 + nf*8 + (lane & 3) * 2;          // 0..127 within tile
        int gcol = n0 + d;
        float b0 = bias[gcol], b1 = bias[gcol + 1];
        #pragma unroll
        for (int mf = 0; mf < 4; ++mf) {
            int row0 = m0 + wm*64 + mf*16 + (lane >> 2);
            #pragma unroll
            for (int half = 0; half < 2; ++half) {
                int row = row0 + half * 8;
                float v0 = acc[mf][nf][half*2 + 0] + b0;
                float v1 = acc[mf][nf][half*2 + 1] + b1;
                if (mode == 3) {
                    *(float2*)(outF + (size_t)row * E_ + gcol) = make_float2(v0, v1);
                } else {
                    int b = row >> 11, t = row & (T_ - 1), h = blockIdx.x;
                    size_t idx = (((size_t)(b*H_ + h)) * T_ + t) * D_ + d;
                    if (mode == 2) {
                        uint32_t hi, lo;
                        split2(v0, v1, hi, lo);
                        *(uint32_t*)&g_Vh[idx] = hi;
                        *(uint32_t*)&g_Vl[idx] = lo;
                    } else {
                        float* dst = (mode == 0) ? g_Q : g_K;
                        *(float2*)(dst + idx) = make_float2(v0, v1);
                    }
                }
            }
        }
    }
}

// ---------------------------------------------------------------------------
// RoPE + scale (Q only).  Q -> f16 hi only; K -> hi/lo split.
// ---------------------------------------------------------------------------
__global__ void rope_split_kernel() {
    const int total = B_*H_*T_*(D_/2);
    int idx = blockIdx.x * blockDim.x + threadIdx.x;
    if (idx >= total) return;
    int row = idx >> 6;
    int j   = idx & 63;
    int t   = row & (T_ - 1);
    float ang = (float)(t + 1) * g_theta[j];
    float s, c;
    sincosf(ang, &s, &c);
    int isK = blockIdx.y;
    const float* src = isK ? g_K : g_Q;
    size_t base = (size_t)row * D_;
    float x0 = src[base + j];
    float x1 = src[base + j + 64];
    float r0 = x0*c - x1*s;
    float r1 = x1*c + x0*s;
    if (isK) {
        __half h0 = __float2half_rn(r0);
        __half h1 = __float2half_rn(r1);
        g_Kh[base + j]      = h0;
        g_Kh[base + j + 64] = h1;
        g_Kl[base + j]      = __float2half_rn(r0 - __half2float(h0));
        g_Kl[base + j + 64] = __float2half_rn(r1 - __half2float(h1));
    } else {
        r0 *= QSCALE; r1 *= QSCALE;
        g_Qh[base + j]      = __float2half_rn(r0);
        g_Qh[base + j + 64] = __float2half_rn(r1);
    }
}

// ---------------------------------------------------------------------------
// Flash attention, causal, 2-pass HMMA (K and V exactly split, Q/P f16),
// fp32 softmax. grid (T/64, B*H), 128 threads (4 warps). BQ=64, BKV=64.
// Heavy q-tiles mapped to low blockIdx for wave-1 start.
// ---------------------------------------------------------------------------
#define AT_ROW 136                       // halves per smem row (128 + 8 pad)
#define AT_TILE (64*AT_ROW)              // halves per matrix
#define ATTN_SMEM (3*AT_TILE*2)          // Qh, KVh, KVl = 52224 B

__global__ __launch_bounds__(128) void attn_tc() {
    extern __shared__ __align__(16) __half asmem[];
    __half* sQh = asmem;
    __half* sKh = asmem + AT_TILE;
    __half* sKl = asmem + 2*AT_TILE;
    const uint32_t uQh = smem_u32(sQh);
    const uint32_t uKh = smem_u32(sKh), uKl = smem_u32(sKl);

    const int tid = threadIdx.x;
    const int lane = tid & 31;
    const int w = tid >> 5;
    const int q0 = (int)(gridDim.x - 1 - blockIdx.x) * 64;   // heavy tiles first
    const int bh = blockIdx.y;
    const __half* Qhp = g_Qh + (size_t)bh * T_ * D_;
    const __half* Khp = g_Kh + (size_t)bh * T_ * D_;
    const __half* Klp = g_Kl + (size_t)bh * T_ * D_;
    const __half* Vhp = g_Vh + (size_t)bh * T_ * D_;
    const __half* Vlp = g_Vl + (size_t)bh * T_ * D_;

    // load Q tile
    #pragma unroll
    for (int p = 0; p < 8; ++p) {
        int idx = tid + p * 128;
        int row = idx >> 4, c8 = idx & 15;
        *(float4*)&sQh[row*AT_ROW + c8*8] = *(const float4*)&Qhp[(size_t)(q0+row)*D_ + c8*8];
    }

    float of[16][4] = {};
    float m0 = -1e30f, m1 = -1e30f, l0 = 0.f, l1 = 0.f;
    const int nblocks = q0/64 + 1;

    for (int it = 0; it < nblocks; ++it) {
        const int k0 = it * 64;
        const bool diag = (it == nblocks - 1);

        __syncthreads();   // prev V reads done (or Q load done on it=0)
        #pragma unroll
        for (int p = 0; p < 8; ++p) {
            int idx = tid + p * 128;
            int row = idx >> 4, c8 = idx & 15;
            *(float4*)&sKh[row*AT_ROW + c8*8] = *(const float4*)&Khp[(size_t)(k0+row)*D_ + c8*8];
            *(float4*)&sKl[row*AT_ROW + c8*8] = *(const float4*)&Klp[(size_t)(k0+row)*D_ + c8*8];
        }
        __syncthreads();

        // ---- S = Q (K_hi + K_lo)^T (2-pass) ----
        float sf[8][4] = {};
        #pragma unroll
        for (int k16 = 0; k16 < 8; ++k16) {
            uint32_t aqh[4];
            uint32_t aaddr = (w*16 + (lane & 15)) * (AT_ROW*2) + k16*32 + (lane >> 4) * 16;
            ldsm4(aqh, uQh + aaddr);
            #pragma unroll
            for (int g = 0; g < 4; ++g) {
                uint32_t kbh[4], kbl[4];
                uint32_t baddr = (g*16 + (lane & 7) + ((lane >> 4) & 1) * 8) * (AT_ROW*2)
                               + k16*32 + ((lane >> 3) & 1) * 16;
                ldsm4(kbh, uKh + baddr);
                ldsm4(kbl, uKl + baddr);
                mma16816(sf[2*g],   aqh, kbh[0], kbh[1]);
                mma16816(sf[2*g],   aqh, kbl[0], kbl[1]);
                mma16816(sf[2*g+1], aqh, kbh[2], kbh[3]);
                mma16816(sf[2*g+1], aqh, kbl[2], kbl[3]);
            }
        }

        // ---- mask (diagonal block only) ----
        const int rg0 = q0 + w*16 + (lane >> 2);
        if (diag) {
            #pragma unroll
            for (int n = 0; n < 8; ++n) {
                int col = k0 + n*8 + (lane & 3) * 2;
                if (col     > rg0)     sf[n][0] = -1e30f;
                if (col + 1 > rg0)     sf[n][1] = -1e30f;
                if (col     > rg0 + 8) sf[n][2] = -1e30f;
                if (col + 1 > rg0 + 8) sf[n][3] = -1e30f;
            }
        }

        // ---- online softmax ----
        float mx0 = -1e30f, mx1 = -1e30f;
        #pragma unroll
        for (int n = 0; n < 8; ++n) {
            mx0 = fmaxf(mx0, fmaxf(sf[n][0], sf[n][1]));
            mx1 = fmaxf(mx1, fmaxf(sf[n][2], sf[n][3]));
        }
        mx0 = qmax(mx0); mx1 = qmax(mx1);
        float mn0 = fmaxf(m0, mx0), mn1 = fmaxf(m1, mx1);
        float a0 = __expf(m0 - mn0), a1 = __expf(m1 - mn1);
        m0 = mn0; m1 = mn1;

        uint32_t pa[4][4];
        float s0 = 0.f, s1 = 0.f;
        #pragma unroll
        for (int n = 0; n < 8; ++n) {
            float p0 = __expf(sf[n][0] - mn0);
            float p1 = __expf(sf[n][1] - mn0);
            float p2 = __expf(sf[n][2] - mn1);
            float p3 = __expf(sf[n][3] - mn1);
            s0 += p0 + p1; s1 += p2 + p3;
            int kt = n >> 1, o = (n & 1) * 2;
            pa[kt][o + 0] = pack2(p0, p1);
            pa[kt][o + 1] = pack2(p2, p3);
        }
        s0 = qsum(s0); s1 = qsum(s1);
        l0 = l0 * a0 + s0;
        l1 = l1 * a1 + s1;
        #pragma unroll
        for (int n = 0; n < 16; ++n) {
            of[n][0] *= a0; of[n][1] *= a0;
            of[n][2] *= a1; of[n][3] *= a1;
        }

        // ---- load V into the K buffers ----
        __syncthreads();
        #pragma unroll
        for (int p = 0; p < 8; ++p) {
            int idx = tid + p * 128;
            int row = idx >> 4, c8 = idx & 15;
            *(float4*)&sKh[row*AT_ROW + c8*8] = *(const float4*)&Vhp[(size_t)(k0+row)*D_ + c8*8];
            *(float4*)&sKl[row*AT_ROW + c8*8] = *(const float4*)&Vlp[(size_t)(k0+row)*D_ + c8*8];
        }
        __syncthreads();

        // ---- O += P (V_hi + V_lo) (2-pass) ----
        #pragma unroll
        for (int kt = 0; kt < 4; ++kt) {
            #pragma unroll
            for (int g = 0; g < 8; ++g) {
                uint32_t vbh[4], vbl[4];
                uint32_t vaddr = (kt*16 + (lane & 7) + ((lane >> 3) & 1) * 8) * (AT_ROW*2)
                               + g*32 + ((lane >> 4) & 1) * 16;
                ldsm4t(vbh, uKh + vaddr);
                ldsm4t(vbl, uKl + vaddr);
                mma16816(of[2*g],   pa[kt], vbh[0], vbh[1]);
                mma16816(of[2*g],   pa[kt], vbl[0], vbl[1]);
                mma16816(of[2*g+1], pa[kt], vbh[2], vbh[3]);
                mma16816(of[2*g+1], pa[kt], vbl[2], vbl[3]);
            }
        }
    }

    // ---- epilogue: normalize, store f16 ----
    float inv0 = 1.0f / l0, inv1 = 1.0f / l1;
    const int b = bh >> 4, h = bh & 15;
    const int row0 = q0 + w*16 + (lane >> 2);
    size_t base0 = ((size_t)(b*T_ + row0)) * E_ + h*D_;
    size_t base1 = base0 + 8 * E_;
    #pragma unroll
    for (int n = 0; n < 16; ++n) {
        int col = n*8 + (lane & 3) * 2;
        *(uint32_t*)&g_Yh[base0 + col] = pack2(of[n][0] * inv0, of[n][1] * inv0);
        *(uint32_t*)&g_Yh[base1 + col] = pack2(of[n][2] * inv1, of[n][3] * inv1);
    }
}

// ---------------------------------------------------------------------------
extern "C" void kernel_launch(void* const* d_in, const int* in_sizes, int n_in,
                              void* d_out, int out_size) {
    const float* x  = (const float*)d_in[0];
    const float* Wq = (const float*)d_in[1];
    const float* bq = (const float*)d_in[2];
    const float* Wk = (const float*)d_in[3];
    const float* bk = (const float*)d_in[4];
    const float* Wv = (const float*)d_in[5];
    const float* bv = (const float*)d_in[6];
    const float* Wo = (const float*)d_in[7];
    const float* bo = (const float*)d_in[8];
    float* out = (float*)d_out;

    cudaFuncSetAttribute(gemm_tc, cudaFuncAttributeMaxDynamicSharedMemorySize, GEMM_SMEM);
    cudaFuncSetAttribute(attn_tc, cudaFuncAttributeMaxDynamicSharedMemorySize, ATTN_SMEM);

    theta_init_kernel<<<1, 64>>>();

    __half *Xh, *Wh, *Wl, *Yh;
    cudaGetSymbolAddress((void**)&Xh, g_Xh);
    cudaGetSymbolAddress((void**)&Wh, g_Wh);
    cudaGetSymbolAddress((void**)&Wl, g_Wl);
    cudaGetSymbolAddress((void**)&Yh, g_Yh);

    f2h_kernel<<<(M_*E_/4 + 255)/256, 256>>>(x, Xh, M_*E_/4);
    split_kernel<<<(WN_/4 + 255)/256, 256>>>(Wq, Wh + 0*(size_t)WN_, Wl + 0*(size_t)WN_, WN_/4);
    split_kernel<<<(WN_/4 + 255)/256, 256>>>(Wk, Wh + 1*(size_t)WN_, Wl + 1*(size_t)WN_, WN_/4);
    split_kernel<<<(WN_/4 + 255)/256, 256>>>(Wv, Wh + 2*(size_t)WN_, Wl + 2*(size_t)WN_, WN_/4);
    split_kernel<<<(WN_/4 + 255)/256, 256>>>(Wo, Wh + 3*(size_t)WN_, Wl + 3*(size_t)WN_, WN_/4);

    dim3 gg(E_/128, M_/128);
    gemm_tc<<<gg, 256, GEMM_SMEM>>>(Xh, Wh + 0*(size_t)WN_, Wl + 0*(size_t)WN_, bq, nullptr, 0);
    gemm_tc<<<gg, 256, GEMM_SMEM>>>(Xh, Wh + 1*(size_t)WN_, Wl + 1*(size_t)WN_, bk, nullptr, 1);
    gemm_tc<<<gg, 256, GEMM_SMEM>>>(Xh, Wh + 2*(size_t)WN_, Wl + 2*(size_t)WN_, bv, nullptr, 2);

    const int rope_total = B_*H_*T_*(D_/2);
    dim3 g2((rope_total + 255)/256, 2);
    rope_split_kernel<<<g2, 256>>>();

    dim3 g3(T_/64, B_*H_);
    attn_tc<<<g3, 128, ATTN_SMEM>>>();

    gemm_tc<<<gg, 256, GEMM_SMEM>>>(Yh, Wh + 3*(size_t)WN_, Wl + 3*(size_t)WN_, bo, out, 3);
}

// round 6
// speedup vs baseline: 7.0965x; 1.4763x over previous
#include <cuda_runtime.h>
#include <cuda_fp16.h>
#include <math.h>
#include <cstdint>

#define B_ 2
#define T_ 2048
#define E_ 2048
#define H_ 16
#define D_ 128
#define M_ (B_*T_)             // 4096
#define QKV_N (B_*H_*T_*D_)    // 8388608
#define WN_ (E_*E_)            // 4194304
#define QSCALE 0.08838834764831845f   // 1/sqrt(128)

// ---------------- scratch ----------------------------------------------------
__device__ float  g_Q[QKV_N];          // fp32 Q (pre-rope), head-major [b,h,t,d]
__device__ float  g_K[QKV_N];
__device__ __half g_Qh[QKV_N];                                  // post-rope, scaled, f16
__device__ __half g_Kh[QKV_N]; __device__ __half g_Kl[QKV_N];   // post-rope, split
__device__ __half g_Vh[QKV_N]; __device__ __half g_Vl[QKV_N];
__device__ __half g_Yh[QKV_N];                                  // attn out [b,t,h*128+d]
__device__ __half g_Xh[M_*E_];
__device__ __half g_Wh[4*WN_];                                  // Wq,Wk,Wv,Wo f16
__device__ float  g_theta[64];

// ---------------- helpers ----------------------------------------------------
__device__ __forceinline__ uint32_t smem_u32(const void* p) {
    uint32_t a;
    asm("{ .reg .u64 t; cvta.to.shared.u64 t, %1; cvt.u32.u64 %0, t; }" : "=r"(a) : "l"(p));
    return a;
}
__device__ __forceinline__ void cp16(uint32_t d, const void* g) {
    asm volatile("cp.async.cg.shared.global [%0], [%1], 16;" :: "r"(d), "l"(g));
}
__device__ __forceinline__ void ldsm4(uint32_t (&r)[4], uint32_t addr) {
    asm volatile("ldmatrix.sync.aligned.m8n8.x4.shared.b16 {%0,%1,%2,%3}, [%4];"
        : "=r"(r[0]), "=r"(r[1]), "=r"(r[2]), "=r"(r[3]) : "r"(addr));
}
__device__ __forceinline__ void ldsm4t(uint32_t (&r)[4], uint32_t addr) {
    asm volatile("ldmatrix.sync.aligned.m8n8.x4.trans.shared.b16 {%0,%1,%2,%3}, [%4];"
        : "=r"(r[0]), "=r"(r[1]), "=r"(r[2]), "=r"(r[3]) : "r"(addr));
}
__device__ __forceinline__ void mma16816(float (&d)[4], const uint32_t (&a)[4],
                                         uint32_t b0, uint32_t b1) {
    asm volatile("mma.sync.aligned.m16n8k16.row.col.f32.f16.f16.f32 "
        "{%0,%1,%2,%3},{%4,%5,%6,%7},{%8,%9},{%0,%1,%2,%3};"
        : "+f"(d[0]), "+f"(d[1]), "+f"(d[2]), "+f"(d[3])
        : "r"(a[0]), "r"(a[1]), "r"(a[2]), "r"(a[3]), "r"(b0), "r"(b1));
}
__device__ __forceinline__ void split2(float x0, float x1, uint32_t& hi, uint32_t& lo) {
    __half2 h = __floats2half2_rn(x0, x1);
    float2 b = __half22float2(h);
    __half2 l = __floats2half2_rn(x0 - b.x, x1 - b.y);
    hi = *(uint32_t*)&h; lo = *(uint32_t*)&l;
}
__device__ __forceinline__ uint32_t pack2(float x0, float x1) {
    __half2 h = __floats2half2_rn(x0, x1);
    return *(uint32_t*)&h;
}
__device__ __forceinline__ float qmax(float v) {
    v = fmaxf(v, __shfl_xor_sync(0xffffffffu, v, 1));
    v = fmaxf(v, __shfl_xor_sync(0xffffffffu, v, 2));
    return v;
}
__device__ __forceinline__ float qsum(float v) {
    v += __shfl_xor_sync(0xffffffffu, v, 1);
    v += __shfl_xor_sync(0xffffffffu, v, 2);
    return v;
}

// ---------------------------------------------------------------------------
__global__ void theta_init_kernel() {
    int j = threadIdx.x;
    if (j < 64) g_theta[j] = (float)pow(10000.0, -(double)j / 64.0);
}

// f32 -> f16
__global__ void f2h_kernel(const float* __restrict__ src, __half* __restrict__ dst, int n4) {
    int i = blockIdx.x * blockDim.x + threadIdx.x;
    if (i < n4) {
        float4 v = ((const float4*)src)[i];
        uint32_t* d = (uint32_t*)dst + (size_t)i * 2;
        d[0] = pack2(v.x, v.y);
        d[1] = pack2(v.z, v.w);
    }
}

// ---------------------------------------------------------------------------
// GEMM core: C tile [128x128] = A[M,K]@W[N,K]^T + bias, plain f16 HMMA, 1 pass.
// BM=BN=128, BK=64, 256 thr (8 warps 2x4), 2-stage cp.async pipeline.
// mode 0: ->g_Q fp32 head-major   mode 1: ->g_K fp32 head-major
// mode 2: ->g_Vh/g_Vl split head-major      mode 3: ->outF fp32 row-major
// ---------------------------------------------------------------------------
#define MAT_B  (128*144)        // bytes per matrix per stage (128 rows x 144B pitch)
#define STAGE_B (2*MAT_B)       // Ah, Wh
#define GEMM_SMEM (2*STAGE_B)   // 73728

__device__ __forceinline__ void gemm_load_stage(
    uint32_t sb, const __half* Ah, const __half* Bh,
    int m0, int n0, int k0, int tid)
{
    #pragma unroll
    for (int mat = 0; mat < 2; ++mat) {
        const __half* src = mat ? Bh : Ah;
        int rbase = mat ? n0 : m0;
        #pragma unroll
        for (int p = 0; p < 4; ++p) {
            int idx = tid + p * 256;
            int row = idx >> 3, c16 = idx & 7;
            const __half* g = src + (size_t)(rbase + row) * E_ + k0 + c16 * 8;
            cp16(sb + mat * MAT_B + row * 144 + c16 * 16, g);
        }
    }
    asm volatile("cp.async.commit_group;" ::: "memory");
}

__device__ __forceinline__ void gemm_core(
    const __half* __restrict__ Ah, const __half* __restrict__ Bh,
    const float* __restrict__ bias, float* __restrict__ outF,
    int mode, uint32_t sbase)
{
    const int tid = threadIdx.x;
    const int lane = tid & 31;
    const int wid = tid >> 5;
    const int wm = wid >> 2, wn = wid & 3;
    const int n0 = blockIdx.x * 128;
    const int m0 = blockIdx.y * 128;

    float acc[4][4][4] = {};

    gemm_load_stage(sbase,           Ah, Bh, m0, n0, 0,  tid);
    gemm_load_stage(sbase + STAGE_B, Ah, Bh, m0, n0, 64, tid);

    for (int i = 0; i < E_/64; ++i) {
        const uint32_t sb = sbase + (i & 1) * STAGE_B;
        asm volatile("cp.async.wait_group 1;" ::: "memory");
        __syncthreads();

        #pragma unroll
        for (int k16 = 0; k16 < 4; ++k16) {
            uint32_t ah[4][4];
            #pragma unroll
            for (int mf = 0; mf < 4; ++mf) {
                uint32_t addr = sb + (wm*64 + mf*16 + (lane & 15)) * 144
                              + k16*32 + (lane >> 4) * 16;
                ldsm4(ah[mf], addr);
            }
            uint32_t bh[2][4];
            #pragma unroll
            for (int g = 0; g < 2; ++g) {
                uint32_t addr = sb + MAT_B
                              + (wn*32 + g*16 + (lane & 7) + ((lane >> 4) & 1) * 8) * 144
                              + k16*32 + ((lane >> 3) & 1) * 16;
                ldsm4(bh[g], addr);
            }
            #pragma unroll
            for (int mf = 0; mf < 4; ++mf)
                #pragma unroll
                for (int nf = 0; nf < 4; ++nf) {
                    int g = nf >> 1, h = (nf & 1) * 2;
                    mma16816(acc[mf][nf], ah[mf], bh[g][h], bh[g][h+1]);
                }
        }
        __syncthreads();
        if (i + 2 < E_/64)
            gemm_load_stage(sb, Ah, Bh, m0, n0, (i + 2) * 64, tid);
        else
            asm volatile("cp.async.commit_group;" ::: "memory");
    }

    // epilogue
    #pragma unroll
    for (int nf = 0; nf < 4; ++nf) {
        int d = wn*32 + nf*8 + (lane & 3) * 2;          // 0..127 within tile
        int gcol = n0 + d;
        float b0 = bias[gcol], b1 = bias[gcol + 1];
        #pragma unroll
        for (int mf = 0; mf < 4; ++mf) {
            int row0 = m0 + wm*64 + mf*16 + (lane >> 2);
            #pragma unroll
            for (int half = 0; half < 2; ++half) {
                int row = row0 + half * 8;
                float v0 = acc[mf][nf][half*2 + 0] + b0;
                float v1 = acc[mf][nf][half*2 + 1] + b1;
                if (mode == 3) {
                    *(float2*)(outF + (size_t)row * E_ + gcol) = make_float2(v0, v1);
                } else {
                    int b = row >> 11, t = row & (T_ - 1), h = blockIdx.x;
                    size_t idx = (((size_t)(b*H_ + h)) * T_ + t) * D_ + d;
                    if (mode == 2) {
                        uint32_t hi, lo;
                        split2(v0, v1, hi, lo);
                        *(uint32_t*)&g_Vh[idx] = hi;
                        *(uint32_t*)&g_Vl[idx] = lo;
                    } else {
                        float* dst = (mode == 0) ? g_Q : g_K;
                        *(float2*)(dst + idx) = make_float2(v0, v1);
                    }
                }
            }
        }
    }
}

// fused Q/K/V projections: grid (16, 32, 3), z selects target
__global__ __launch_bounds__(256) void qkv_gemm(
    const float* __restrict__ bq, const float* __restrict__ bk,
    const float* __restrict__ bv)
{
    extern __shared__ __align__(16) char dsmem[];
    const int mode = blockIdx.z;
    const float* bias = (mode == 0) ? bq : (mode == 1) ? bk : bv;
    gemm_core(g_Xh, g_Wh + (size_t)mode * WN_, bias, nullptr, mode, smem_u32(dsmem));
}

// output projection: grid (16, 32)
__global__ __launch_bounds__(256) void out_gemm(
    const float* __restrict__ bo, float* __restrict__ outF)
{
    extern __shared__ __align__(16) char dsmem[];
    gemm_core(g_Yh, g_Wh + 3*(size_t)WN_, bo, outF, 3, smem_u32(dsmem));
}

// ---------------------------------------------------------------------------
// RoPE + scale (Q only).  Q -> f16 hi only; K -> hi/lo split.
// ---------------------------------------------------------------------------
__global__ void rope_split_kernel() {
    const int total = B_*H_*T_*(D_/2);
    int idx = blockIdx.x * blockDim.x + threadIdx.x;
    if (idx >= total) return;
    int row = idx >> 6;
    int j   = idx & 63;
    int t   = row & (T_ - 1);
    float ang = (float)(t + 1) * g_theta[j];
    float s, c;
    sincosf(ang, &s, &c);
    int isK = blockIdx.y;
    const float* src = isK ? g_K : g_Q;
    size_t base = (size_t)row * D_;
    float x0 = src[base + j];
    float x1 = src[base + j + 64];
    float r0 = x0*c - x1*s;
    float r1 = x1*c + x0*s;
    if (isK) {
        __half h0 = __float2half_rn(r0);
        __half h1 = __float2half_rn(r1);
        g_Kh[base + j]      = h0;
        g_Kh[base + j + 64] = h1;
        g_Kl[base + j]      = __float2half_rn(r0 - __half2float(h0));
        g_Kl[base + j + 64] = __float2half_rn(r1 - __half2float(h1));
    } else {
        r0 *= QSCALE; r1 *= QSCALE;
        g_Qh[base + j]      = __float2half_rn(r0);
        g_Qh[base + j + 64] = __float2half_rn(r1);
    }
}

// ---------------------------------------------------------------------------
// Flash attention, causal, 2-pass HMMA (K and V exactly split, Q/P f16),
// fp32 softmax. grid (T/64, B*H), 128 threads (4 warps). BQ=64, BKV=64.
// Heavy q-tiles mapped to low blockIdx for wave-1 start.
// ---------------------------------------------------------------------------
#define AT_ROW 136                       // halves per smem row (128 + 8 pad)
#define AT_TILE (64*AT_ROW)              // halves per matrix
#define ATTN_SMEM (3*AT_TILE*2)          // Qh, KVh, KVl = 52224 B

__global__ __launch_bounds__(128) void attn_tc() {
    extern __shared__ __align__(16) __half asmem[];
    __half* sQh = asmem;
    __half* sKh = asmem + AT_TILE;
    __half* sKl = asmem + 2*AT_TILE;
    const uint32_t uQh = smem_u32(sQh);
    const uint32_t uKh = smem_u32(sKh), uKl = smem_u32(sKl);

    const int tid = threadIdx.x;
    const int lane = tid & 31;
    const int w = tid >> 5;
    const int q0 = (int)(gridDim.x - 1 - blockIdx.x) * 64;   // heavy tiles first
    const int bh = blockIdx.y;
    const __half* Qhp = g_Qh + (size_t)bh * T_ * D_;
    const __half* Khp = g_Kh + (size_t)bh * T_ * D_;
    const __half* Klp = g_Kl + (size_t)bh * T_ * D_;
    const __half* Vhp = g_Vh + (size_t)bh * T_ * D_;
    const __half* Vlp = g_Vl + (size_t)bh * T_ * D_;

    // load Q tile
    #pragma unroll
    for (int p = 0; p < 8; ++p) {
        int idx = tid + p * 128;
        int row = idx >> 4, c8 = idx & 15;
        *(float4*)&sQh[row*AT_ROW + c8*8] = *(const float4*)&Qhp[(size_t)(q0+row)*D_ + c8*8];
    }

    float of[16][4] = {};
    float m0 = -1e30f, m1 = -1e30f, l0 = 0.f, l1 = 0.f;
    const int nblocks = q0/64 + 1;

    for (int it = 0; it < nblocks; ++it) {
        const int k0 = it * 64;
        const bool diag = (it == nblocks - 1);

        __syncthreads();   // prev V reads done (or Q load done on it=0)
        #pragma unroll
        for (int p = 0; p < 8; ++p) {
            int idx = tid + p * 128;
            int row = idx >> 4, c8 = idx & 15;
            *(float4*)&sKh[row*AT_ROW + c8*8] = *(const float4*)&Khp[(size_t)(k0+row)*D_ + c8*8];
            *(float4*)&sKl[row*AT_ROW + c8*8] = *(const float4*)&Klp[(size_t)(k0+row)*D_ + c8*8];
        }
        __syncthreads();

        // ---- S = Q (K_hi + K_lo)^T (2-pass) ----
        float sf[8][4] = {};
        #pragma unroll
        for (int k16 = 0; k16 < 8; ++k16) {
            uint32_t aqh[4];
            uint32_t aaddr = (w*16 + (lane & 15)) * (AT_ROW*2) + k16*32 + (lane >> 4) * 16;
            ldsm4(aqh, uQh + aaddr);
            #pragma unroll
            for (int g = 0; g < 4; ++g) {
                uint32_t kbh[4], kbl[4];
                uint32_t baddr = (g*16 + (lane & 7) + ((lane >> 4) & 1) * 8) * (AT_ROW*2)
                               + k16*32 + ((lane >> 3) & 1) * 16;
                ldsm4(kbh, uKh + baddr);
                ldsm4(kbl, uKl + baddr);
                mma16816(sf[2*g],   aqh, kbh[0], kbh[1]);
                mma16816(sf[2*g],   aqh, kbl[0], kbl[1]);
                mma16816(sf[2*g+1], aqh, kbh[2], kbh[3]);
                mma16816(sf[2*g+1], aqh, kbl[2], kbl[3]);
            }
        }

        // ---- mask (diagonal block only) ----
        const int rg0 = q0 + w*16 + (lane >> 2);
        if (diag) {
            #pragma unroll
            for (int n = 0; n < 8; ++n) {
                int col = k0 + n*8 + (lane & 3) * 2;
                if (col     > rg0)     sf[n][0] = -1e30f;
                if (col + 1 > rg0)     sf[n][1] = -1e30f;
                if (col     > rg0 + 8) sf[n][2] = -1e30f;
                if (col + 1 > rg0 + 8) sf[n][3] = -1e30f;
            }
        }

        // ---- online softmax ----
        float mx0 = -1e30f, mx1 = -1e30f;
        #pragma unroll
        for (int n = 0; n < 8; ++n) {
            mx0 = fmaxf(mx0, fmaxf(sf[n][0], sf[n][1]));
            mx1 = fmaxf(mx1, fmaxf(sf[n][2], sf[n][3]));
        }
        mx0 = qmax(mx0); mx1 = qmax(mx1);
        float mn0 = fmaxf(m0, mx0), mn1 = fmaxf(m1, mx1);
        float a0 = __expf(m0 - mn0), a1 = __expf(m1 - mn1);
        m0 = mn0; m1 = mn1;

        uint32_t pa[4][4];
        float s0 = 0.f, s1 = 0.f;
        #pragma unroll
        for (int n = 0; n < 8; ++n) {
            float p0 = __expf(sf[n][0] - mn0);
            float p1 = __expf(sf[n][1] - mn0);
            float p2 = __expf(sf[n][2] - mn1);
            float p3 = __expf(sf[n][3] - mn1);
            s0 += p0 + p1; s1 += p2 + p3;
            int kt = n >> 1, o = (n & 1) * 2;
            pa[kt][o + 0] = pack2(p0, p1);
            pa[kt][o + 1] = pack2(p2, p3);
        }
        s0 = qsum(s0); s1 = qsum(s1);
        l0 = l0 * a0 + s0;
        l1 = l1 * a1 + s1;
        #pragma unroll
        for (int n = 0; n < 16; ++n) {
            of[n][0] *= a0; of[n][1] *= a0;
            of[n][2] *= a1; of[n][3] *= a1;
        }

        // ---- load V into the K buffers ----
        __syncthreads();
        #pragma unroll
        for (int p = 0; p < 8; ++p) {
            int idx = tid + p * 128;
            int row = idx >> 4, c8 = idx & 15;
            *(float4*)&sKh[row*AT_ROW + c8*8] = *(const float4*)&Vhp[(size_t)(k0+row)*D_ + c8*8];
            *(float4*)&sKl[row*AT_ROW + c8*8] = *(const float4*)&Vlp[(size_t)(k0+row)*D_ + c8*8];
        }
        __syncthreads();

        // ---- O += P (V_hi + V_lo) (2-pass) ----
        #pragma unroll
        for (int kt = 0; kt < 4; ++kt) {
            #pragma unroll
            for (int g = 0; g < 8; ++g) {
                uint32_t vbh[4], vbl[4];
                uint32_t vaddr = (kt*16 + (lane & 7) + ((lane >> 3) & 1) * 8) * (AT_ROW*2)
                               + g*32 + ((lane >> 4) & 1) * 16;
                ldsm4t(vbh, uKh + vaddr);
                ldsm4t(vbl, uKl + vaddr);
                mma16816(of[2*g],   pa[kt], vbh[0], vbh[1]);
                mma16816(of[2*g],   pa[kt], vbl[0], vbl[1]);
                mma16816(of[2*g+1], pa[kt], vbh[2], vbh[3]);
                mma16816(of[2*g+1], pa[kt], vbl[2], vbl[3]);
            }
        }
    }

    // ---- epilogue: normalize, store f16 ----
    float inv0 = 1.0f / l0, inv1 = 1.0f / l1;
    const int b = bh >> 4, h = bh & 15;
    const int row0 = q0 + w*16 + (lane >> 2);
    size_t base0 = ((size_t)(b*T_ + row0)) * E_ + h*D_;
    size_t base1 = base0 + 8 * E_;
    #pragma unroll
    for (int n = 0; n < 16; ++n) {
        int col = n*8 + (lane & 3) * 2;
        *(uint32_t*)&g_Yh[base0 + col] = pack2(of[n][0] * inv0, of[n][1] * inv0);
        *(uint32_t*)&g_Yh[base1 + col] = pack2(of[n][2] * inv1, of[n][3] * inv1);
    }
}

// ---------------------------------------------------------------------------
extern "C" void kernel_launch(void* const* d_in, const int* in_sizes, int n_in,
                              void* d_out, int out_size) {
    const float* x  = (const float*)d_in[0];
    const float* Wq = (const float*)d_in[1];
    const float* bq = (const float*)d_in[2];
    const float* Wk = (const float*)d_in[3];
    const float* bk = (const float*)d_in[4];
    const float* Wv = (const float*)d_in[5];
    const float* bv = (const float*)d_in[6];
    const float* Wo = (const float*)d_in[7];
    const float* bo = (const float*)d_in[8];
    float* out = (float*)d_out;

    cudaFuncSetAttribute(qkv_gemm, cudaFuncAttributeMaxDynamicSharedMemorySize, GEMM_SMEM);
    cudaFuncSetAttribute(out_gemm, cudaFuncAttributeMaxDynamicSharedMemorySize, GEMM_SMEM);
    cudaFuncSetAttribute(attn_tc,  cudaFuncAttributeMaxDynamicSharedMemorySize, ATTN_SMEM);

    theta_init_kernel<<<1, 64>>>();

    __half *Xh, *Wh;
    cudaGetSymbolAddress((void**)&Xh, g_Xh);
    cudaGetSymbolAddress((void**)&Wh, g_Wh);

    f2h_kernel<<<(M_*E_/4 + 255)/256, 256>>>(x, Xh, M_*E_/4);
    f2h_kernel<<<(WN_/4 + 255)/256, 256>>>(Wq, Wh + 0*(size_t)WN_, WN_/4);
    f2h_kernel<<<(WN_/4 + 255)/256, 256>>>(Wk, Wh + 1*(size_t)WN_, WN_/4);
    f2h_kernel<<<(WN_/4 + 255)/256, 256>>>(Wv, Wh + 2*(size_t)WN_, WN_/4);
    f2h_kernel<<<(WN_/4 + 255)/256, 256>>>(Wo, Wh + 3*(size_t)WN_, WN_/4);

    dim3 gq(E_/128, M_/128, 3);
    qkv_gemm<<<gq, 256, GEMM_SMEM>>>(bq, bk, bv);

    const int rope_total = B_*H_*T_*(D_/2);
    dim3 g2((rope_total + 255)/256, 2);
    rope_split_kernel<<<g2, 256>>>();

    dim3 g3(T_/64, B_*H_);
    attn_tc<<<g3, 128, ATTN_SMEM>>>();

    dim3 go(E_/128, M_/128);
    out_gemm<<<go, 256, GEMM_SMEM>>>(bo, out);
}

// round 7
// speedup vs baseline: 8.4789x; 1.1948x over previous
#include <cuda_runtime.h>
#include <cuda_fp16.h>
#include <math.h>
#include <cstdint>

#define B_ 2
#define T_ 2048
#define E_ 2048
#define H_ 16
#define D_ 128
#define M_ (B_*T_)             // 4096
#define QKV_N (B_*H_*T_*D_)    // 8388608
#define WN_ (E_*E_)            // 4194304
#define QSCALE 0.08838834764831845f   // 1/sqrt(128)

// ---------------- scratch ----------------------------------------------------
__device__ float  g_Q[QKV_N];          // fp32 Q (pre-rope), head-major [b,h,t,d]
__device__ float  g_K[QKV_N];
__device__ __half g_Qh[QKV_N];         // post-rope, scaled, f16
__device__ __half g_Kh[QKV_N];         // post-rope, f16
__device__ __half g_Vh[QKV_N];
__device__ __half g_Yh[QKV_N];         // attn out [b,t,h*128+d]
__device__ __half g_Xh[M_*E_];
__device__ __half g_Wh[4*WN_];         // Wq,Wk,Wv,Wo f16
__device__ float  g_theta[64];

// ---------------- helpers ----------------------------------------------------
__device__ __forceinline__ uint32_t smem_u32(const void* p) {
    uint32_t a;
    asm("{ .reg .u64 t; cvta.to.shared.u64 t, %1; cvt.u32.u64 %0, t; }" : "=r"(a) : "l"(p));
    return a;
}
__device__ __forceinline__ void cp16(uint32_t d, const void* g) {
    asm volatile("cp.async.cg.shared.global [%0], [%1], 16;" :: "r"(d), "l"(g));
}
__device__ __forceinline__ void ldsm4(uint32_t (&r)[4], uint32_t addr) {
    asm volatile("ldmatrix.sync.aligned.m8n8.x4.shared.b16 {%0,%1,%2,%3}, [%4];"
        : "=r"(r[0]), "=r"(r[1]), "=r"(r[2]), "=r"(r[3]) : "r"(addr));
}
__device__ __forceinline__ void ldsm4t(uint32_t (&r)[4], uint32_t addr) {
    asm volatile("ldmatrix.sync.aligned.m8n8.x4.trans.shared.b16 {%0,%1,%2,%3}, [%4];"
        : "=r"(r[0]), "=r"(r[1]), "=r"(r[2]), "=r"(r[3]) : "r"(addr));
}
__device__ __forceinline__ void mma16816(float (&d)[4], const uint32_t (&a)[4],
                                         uint32_t b0, uint32_t b1) {
    asm volatile("mma.sync.aligned.m16n8k16.row.col.f32.f16.f16.f32 "
        "{%0,%1,%2,%3},{%4,%5,%6,%7},{%8,%9},{%0,%1,%2,%3};"
        : "+f"(d[0]), "+f"(d[1]), "+f"(d[2]), "+f"(d[3])
        : "r"(a[0]), "r"(a[1]), "r"(a[2]), "r"(a[3]), "r"(b0), "r"(b1));
}
__device__ __forceinline__ uint32_t pack2(float x0, float x1) {
    __half2 h = __floats2half2_rn(x0, x1);
    return *(uint32_t*)&h;
}
__device__ __forceinline__ float qmax(float v) {
    v = fmaxf(v, __shfl_xor_sync(0xffffffffu, v, 1));
    v = fmaxf(v, __shfl_xor_sync(0xffffffffu, v, 2));
    return v;
}
__device__ __forceinline__ float qsum(float v) {
    v += __shfl_xor_sync(0xffffffffu, v, 1);
    v += __shfl_xor_sync(0xffffffffu, v, 2);
    return v;
}

// ---------------------------------------------------------------------------
__global__ void theta_init_kernel() {
    int j = threadIdx.x;
    if (j < 64) g_theta[j] = (float)pow(10000.0, -(double)j / 64.0);
}

// x f32 -> f16
__global__ void f2h_kernel(const float* __restrict__ src, __half* __restrict__ dst, int n4) {
    int i = blockIdx.x * blockDim.x + threadIdx.x;
    if (i < n4) {
        float4 v = ((const float4*)src)[i];
        uint32_t* d = (uint32_t*)dst + (size_t)i * 2;
        d[0] = pack2(v.x, v.y);
        d[1] = pack2(v.z, v.w);
    }
}

// all 4 weights f32 -> f16, one launch. grid.y selects matrix.
__global__ void w_f2h_kernel(const float* __restrict__ w0, const float* __restrict__ w1,
                             const float* __restrict__ w2, const float* __restrict__ w3) {
    int i = blockIdx.x * blockDim.x + threadIdx.x;
    if (i >= WN_/4) return;
    const float* srcs[4] = { w0, w1, w2, w3 };
    const float* src = srcs[blockIdx.y];
    float4 v = ((const float4*)src)[i];
    uint32_t* d = (uint32_t*)(g_Wh + (size_t)blockIdx.y * WN_) + (size_t)i * 2;
    d[0] = pack2(v.x, v.y);
    d[1] = pack2(v.z, v.w);
}

// ---------------------------------------------------------------------------
// GEMM core: C tile [128x128] = A[M,K]@W[N,K]^T + bias, plain f16 HMMA.
// BM=BN=128, BK=64, 256 thr (8 warps 2x4), 2-stage cp.async pipeline.
// mode 0: ->g_Q fp32 head-major   mode 1: ->g_K fp32 head-major
// mode 2: ->g_Vh f16 head-major   mode 3: ->outF fp32 row-major
// ---------------------------------------------------------------------------
#define MAT_B  (128*144)        // bytes per matrix per stage (128 rows x 144B pitch)
#define STAGE_B (2*MAT_B)       // Ah, Wh
#define GEMM_SMEM (2*STAGE_B)   // 73728

__device__ __forceinline__ void gemm_load_stage(
    uint32_t sb, const __half* Ah, const __half* Bh,
    int m0, int n0, int k0, int tid)
{
    #pragma unroll
    for (int mat = 0; mat < 2; ++mat) {
        const __half* src = mat ? Bh : Ah;
        int rbase = mat ? n0 : m0;
        #pragma unroll
        for (int p = 0; p < 4; ++p) {
            int idx = tid + p * 256;
            int row = idx >> 3, c16 = idx & 7;
            const __half* g = src + (size_t)(rbase + row) * E_ + k0 + c16 * 8;
            cp16(sb + mat * MAT_B + row * 144 + c16 * 16, g);
        }
    }
    asm volatile("cp.async.commit_group;" ::: "memory");
}

__device__ __forceinline__ void gemm_core(
    const __half* __restrict__ Ah, const __half* __restrict__ Bh,
    const float* __restrict__ bias, float* __restrict__ outF,
    int mode, uint32_t sbase)
{
    const int tid = threadIdx.x;
    const int lane = tid & 31;
    const int wid = tid >> 5;
    const int wm = wid >> 2, wn = wid & 3;
    const int n0 = blockIdx.x * 128;
    const int m0 = blockIdx.y * 128;

    float acc[4][4][4] = {};

    gemm_load_stage(sbase,           Ah, Bh, m0, n0, 0,  tid);
    gemm_load_stage(sbase + STAGE_B, Ah, Bh, m0, n0, 64, tid);

    for (int i = 0; i < E_/64; ++i) {
        const uint32_t sb = sbase + (i & 1) * STAGE_B;
        asm volatile("cp.async.wait_group 1;" ::: "memory");
        __syncthreads();

        #pragma unroll
        for (int k16 = 0; k16 < 4; ++k16) {
            uint32_t ah[4][4];
            #pragma unroll
            for (int mf = 0; mf < 4; ++mf) {
                uint32_t addr = sb + (wm*64 + mf*16 + (lane & 15)) * 144
                              + k16*32 + (lane >> 4) * 16;
                ldsm4(ah[mf], addr);
            }
            uint32_t bh[2][4];
            #pragma unroll
            for (int g = 0; g < 2; ++g) {
                uint32_t addr = sb + MAT_B
                              + (wn*32 + g*16 + (lane & 7) + ((lane >> 4) & 1) * 8) * 144
                              + k16*32 + ((lane >> 3) & 1) * 16;
                ldsm4(bh[g], addr);
            }
            #pragma unroll
            for (int mf = 0; mf < 4; ++mf)
                #pragma unroll
                for (int nf = 0; nf < 4; ++nf) {
                    int g = nf >> 1, h = (nf & 1) * 2;
                    mma16816(acc[mf][nf], ah[mf], bh[g][h], bh[g][h+1]);
                }
        }
        __syncthreads();
        if (i + 2 < E_/64)
            gemm_load_stage(sb, Ah, Bh, m0, n0, (i + 2) * 64, tid);
        else
            asm volatile("cp.async.commit_group;" ::: "memory");
    }

    // epilogue
    #pragma unroll
    for (int nf = 0; nf < 4; ++nf) {
        int d = wn*32 + nf*8 + (lane & 3) * 2;          // 0..127 within tile
        int gcol = n0 + d;
        float b0 = bias[gcol], b1 = bias[gcol + 1];
        #pragma unroll
        for (int mf = 0; mf < 4; ++mf) {
            int row0 = m0 + wm*64 + mf*16 + (lane >> 2);
            #pragma unroll
            for (int half = 0; half < 2; ++half) {
                int row = row0 + half * 8;
                float v0 = acc[mf][nf][half*2 + 0] + b0;
                float v1 = acc[mf][nf][half*2 + 1] + b1;
                if (mode == 3) {
                    *(float2*)(outF + (size_t)row * E_ + gcol) = make_float2(v0, v1);
                } else {
                    int b = row >> 11, t = row & (T_ - 1), h = blockIdx.x;
                    size_t idx = (((size_t)(b*H_ + h)) * T_ + t) * D_ + d;
                    if (mode == 2) {
                        *(uint32_t*)&g_Vh[idx] = pack2(v0, v1);
                    } else {
                        float* dst = (mode == 0) ? g_Q : g_K;
                        *(float2*)(dst + idx) = make_float2(v0, v1);
                    }
                }
            }
        }
    }
}

// fused Q/K/V projections: grid (16, 32, 3), z selects target
__global__ __launch_bounds__(256) void qkv_gemm(
    const float* __restrict__ bq, const float* __restrict__ bk,
    const float* __restrict__ bv)
{
    extern __shared__ __align__(16) char dsmem[];
    const int mode = blockIdx.z;
    const float* bias = (mode == 0) ? bq : (mode == 1) ? bk : bv;
    gemm_core(g_Xh, g_Wh + (size_t)mode * WN_, bias, nullptr, mode, smem_u32(dsmem));
}

// output projection: grid (16, 32)
__global__ __launch_bounds__(256) void out_gemm(
    const float* __restrict__ bo, float* __restrict__ outF)
{
    extern __shared__ __align__(16) char dsmem[];
    gemm_core(g_Yh, g_Wh + 3*(size_t)WN_, bo, outF, 3, smem_u32(dsmem));
}

// ---------------------------------------------------------------------------
// RoPE + scale (Q only) -> f16.
// ---------------------------------------------------------------------------
__global__ void rope_kernel() {
    const int total = B_*H_*T_*(D_/2);
    int idx = blockIdx.x * blockDim.x + threadIdx.x;
    if (idx >= total) return;
    int row = idx >> 6;
    int j   = idx & 63;
    int t   = row & (T_ - 1);
    float ang = (float)(t + 1) * g_theta[j];
    float s, c;
    sincosf(ang, &s, &c);
    int isK = blockIdx.y;
    const float* src = isK ? g_K : g_Q;
    __half* dst = isK ? g_Kh : g_Qh;
    size_t base = (size_t)row * D_;
    float x0 = src[base + j];
    float x1 = src[base + j + 64];
    float r0 = x0*c - x1*s;
    float r1 = x1*c + x0*s;
    if (!isK) { r0 *= QSCALE; r1 *= QSCALE; }
    dst[base + j]      = __float2half_rn(r0);
    dst[base + j + 64] = __float2half_rn(r1);
}

// ---------------------------------------------------------------------------
// Flash attention, causal, 1-pass f16 HMMA, fp32 softmax.
// grid (T/64, B*H), 128 threads (4 warps). BQ=64 (16 rows/warp), BKV=64.
// K and V time-share one smem tile. Heavy q-tiles mapped to low blockIdx.
// ---------------------------------------------------------------------------
#define AT_ROW 136                       // halves per smem row (128 + 8 pad)
#define AT_TILE (64*AT_ROW)              // halves per matrix
#define ATTN_SMEM (2*AT_TILE*2)          // Qh, KV = 34816 B

__global__ __launch_bounds__(128) void attn_tc() {
    extern __shared__ __align__(16) __half asmem[];
    __half* sQh = asmem;
    __half* sKV = asmem + AT_TILE;
    const uint32_t uQh = smem_u32(sQh);
    const uint32_t uKV = smem_u32(sKV);

    const int tid = threadIdx.x;
    const int lane = tid & 31;
    const int w = tid >> 5;
    const int q0 = (int)(gridDim.x - 1 - blockIdx.x) * 64;   // heavy tiles first
    const int bh = blockIdx.y;
    const __half* Qhp = g_Qh + (size_t)bh * T_ * D_;
    const __half* Khp = g_Kh + (size_t)bh * T_ * D_;
    const __half* Vhp = g_Vh + (size_t)bh * T_ * D_;

    // load Q tile
    #pragma unroll
    for (int p = 0; p < 8; ++p) {
        int idx = tid + p * 128;
        int row = idx >> 4, c8 = idx & 15;
        *(float4*)&sQh[row*AT_ROW + c8*8] = *(const float4*)&Qhp[(size_t)(q0+row)*D_ + c8*8];
    }

    float of[16][4] = {};
    float m0 = -1e30f, m1 = -1e30f, l0 = 0.f, l1 = 0.f;
    const int nblocks = q0/64 + 1;

    for (int it = 0; it < nblocks; ++it) {
        const int k0 = it * 64;
        const bool diag = (it == nblocks - 1);

        __syncthreads();   // prev V reads done (or Q load done on it=0)
        #pragma unroll
        for (int p = 0; p < 8; ++p) {
            int idx = tid + p * 128;
            int row = idx >> 4, c8 = idx & 15;
            *(float4*)&sKV[row*AT_ROW + c8*8] = *(const float4*)&Khp[(size_t)(k0+row)*D_ + c8*8];
        }
        __syncthreads();

        // ---- S = Q K^T ----
        float sf[8][4] = {};
        #pragma unroll
        for (int k16 = 0; k16 < 8; ++k16) {
            uint32_t aqh[4];
            uint32_t aaddr = (w*16 + (lane & 15)) * (AT_ROW*2) + k16*32 + (lane >> 4) * 16;
            ldsm4(aqh, uQh + aaddr);
            #pragma unroll
            for (int g = 0; g < 4; ++g) {
                uint32_t kbh[4];
                uint32_t baddr = (g*16 + (lane & 7) + ((lane >> 4) & 1) * 8) * (AT_ROW*2)
                               + k16*32 + ((lane >> 3) & 1) * 16;
                ldsm4(kbh, uKV + baddr);
                mma16816(sf[2*g],   aqh, kbh[0], kbh[1]);
                mma16816(sf[2*g+1], aqh, kbh[2], kbh[3]);
            }
        }

        // ---- mask (diagonal block only) ----
        const int rg0 = q0 + w*16 + (lane >> 2);
        if (diag) {
            #pragma unroll
            for (int n = 0; n < 8; ++n) {
                int col = k0 + n*8 + (lane & 3) * 2;
                if (col     > rg0)     sf[n][0] = -1e30f;
                if (col + 1 > rg0)     sf[n][1] = -1e30f;
                if (col     > rg0 + 8) sf[n][2] = -1e30f;
                if (col + 1 > rg0 + 8) sf[n][3] = -1e30f;
            }
        }

        // ---- online softmax ----
        float mx0 = -1e30f, mx1 = -1e30f;
        #pragma unroll
        for (int n = 0; n < 8; ++n) {
            mx0 = fmaxf(mx0, fmaxf(sf[n][0], sf[n][1]));
            mx1 = fmaxf(mx1, fmaxf(sf[n][2], sf[n][3]));
        }
        mx0 = qmax(mx0); mx1 = qmax(mx1);
        float mn0 = fmaxf(m0, mx0), mn1 = fmaxf(m1, mx1);
        float a0 = __expf(m0 - mn0), a1 = __expf(m1 - mn1);
        m0 = mn0; m1 = mn1;

        uint32_t pa[4][4];
        float s0 = 0.f, s1 = 0.f;
        #pragma unroll
        for (int n = 0; n < 8; ++n) {
            float p0 = __expf(sf[n][0] - mn0);
            float p1 = __expf(sf[n][1] - mn0);
            float p2 = __expf(sf[n][2] - mn1);
            float p3 = __expf(sf[n][3] - mn1);
            s0 += p0 + p1; s1 += p2 + p3;
            int kt = n >> 1, o = (n & 1) * 2;
            pa[kt][o + 0] = pack2(p0, p1);
            pa[kt][o + 1] = pack2(p2, p3);
        }
        s0 = qsum(s0); s1 = qsum(s1);
        l0 = l0 * a0 + s0;
        l1 = l1 * a1 + s1;
        #pragma unroll
        for (int n = 0; n < 16; ++n) {
            of[n][0] *= a0; of[n][1] *= a0;
            of[n][2] *= a1; of[n][3] *= a1;
        }

        // ---- load V into the KV buffer ----
        __syncthreads();
        #pragma unroll
        for (int p = 0; p < 8; ++p) {
            int idx = tid + p * 128;
            int row = idx >> 4, c8 = idx & 15;
            *(float4*)&sKV[row*AT_ROW + c8*8] = *(const float4*)&Vhp[(size_t)(k0+row)*D_ + c8*8];
        }
        __syncthreads();

        // ---- O += P V ----
        #pragma unroll
        for (int kt = 0; kt < 4; ++kt) {
            #pragma unroll
            for (int g = 0; g < 8; ++g) {
                uint32_t vbh[4];
                uint32_t vaddr = (kt*16 + (lane & 7) + ((lane >> 3) & 1) * 8) * (AT_ROW*2)
                               + g*32 + ((lane >> 4) & 1) * 16;
                ldsm4t(vbh, uKV + vaddr);
                mma16816(of[2*g],   pa[kt], vbh[0], vbh[1]);
                mma16816(of[2*g+1], pa[kt], vbh[2], vbh[3]);
            }
        }
    }

    // ---- epilogue: normalize, store f16 ----
    float inv0 = 1.0f / l0, inv1 = 1.0f / l1;
    const int b = bh >> 4, h = bh & 15;
    const int row0 = q0 + w*16 + (lane >> 2);
    size_t base0 = ((size_t)(b*T_ + row0)) * E_ + h*D_;
    size_t base1 = base0 + 8 * E_;
    #pragma unroll
    for (int n = 0; n < 16; ++n) {
        int col = n*8 + (lane & 3) * 2;
        *(uint32_t*)&g_Yh[base0 + col] = pack2(of[n][0] * inv0, of[n][1] * inv0);
        *(uint32_t*)&g_Yh[base1 + col] = pack2(of[n][2] * inv1, of[n][3] * inv1);
    }
}

// ---------------------------------------------------------------------------
extern "C" void kernel_launch(void* const* d_in, const int* in_sizes, int n_in,
                              void* d_out, int out_size) {
    const float* x  = (const float*)d_in[0];
    const float* Wq = (const float*)d_in[1];
    const float* bq = (const float*)d_in[2];
    const float* Wk = (const float*)d_in[3];
    const float* bk = (const float*)d_in[4];
    const float* Wv = (const float*)d_in[5];
    const float* bv = (const float*)d_in[6];
    const float* Wo = (const float*)d_in[7];
    const float* bo = (const float*)d_in[8];
    float* out = (float*)d_out;

    cudaFuncSetAttribute(qkv_gemm, cudaFuncAttributeMaxDynamicSharedMemorySize, GEMM_SMEM);
    cudaFuncSetAttribute(out_gemm, cudaFuncAttributeMaxDynamicSharedMemorySize, GEMM_SMEM);
    cudaFuncSetAttribute(attn_tc,  cudaFuncAttributeMaxDynamicSharedMemorySize, ATTN_SMEM);

    theta_init_kernel<<<1, 64>>>();

    __half* Xh;
    cudaGetSymbolAddress((void**)&Xh, g_Xh);

    f2h_kernel<<<(M_*E_/4 + 255)/256, 256>>>(x, Xh, M_*E_/4);
    dim3 gw((WN_/4 + 255)/256, 4);
    w_f2h_kernel<<<gw, 256>>>(Wq, Wk, Wv, Wo);

    dim3 gq(E_/128, M_/128, 3);
    qkv_gemm<<<gq, 256, GEMM_SMEM>>>(bq, bk, bv);

    const int rope_total = B_*H_*T_*(D_/2);
    dim3 g2((rope_total + 255)/256, 2);
    rope_kernel<<<g2, 256>>>();

    dim3 g3(T_/64, B_*H_);
    attn_tc<<<g3, 128, ATTN_SMEM>>>();

    dim3 go(E_/128, M_/128);
    out_gemm<<<go, 256, GEMM_SMEM>>>(bo, out);
}

// round 9
// speedup vs baseline: 8.7223x; 1.0287x over previous
#include <cuda_runtime.h>
#include <cuda_fp16.h>
#include <math.h>
#include <cstdint>

#define B_ 2
#define T_ 2048
#define E_ 2048
#define H_ 16
#define D_ 128
#define M_ (B_*T_)             // 4096
#define QKV_N (B_*H_*T_*D_)    // 8388608
#define WN_ (E_*E_)            // 4194304
#define QSCALE 0.08838834764831845f   // 1/sqrt(128)

// ---------------- scratch ----------------------------------------------------
__device__ float  g_Q[QKV_N];          // fp32 Q (pre-rope), head-major [b,h,t,d]
__device__ float  g_K[QKV_N];
__device__ __half g_Qh[QKV_N];         // post-rope, scaled, f16
__device__ __half g_Kh[QKV_N];         // post-rope, f16
__device__ __half g_Vh[QKV_N];
__device__ __half g_Yh[QKV_N];         // attn out [b,t,h*128+d]
__device__ __half g_Xh[M_*E_];
__device__ __half g_Wh[4*WN_];         // Wq,Wk,Wv,Wo f16
__device__ float  g_theta[64];

// ---------------- helpers ----------------------------------------------------
__device__ __forceinline__ uint32_t smem_u32(const void* p) {
    uint32_t a;
    asm("{ .reg .u64 t; cvta.to.shared.u64 t, %1; cvt.u32.u64 %0, t; }" : "=r"(a) : "l"(p));
    return a;
}
__device__ __forceinline__ void cp16(uint32_t d, const void* g) {
    asm volatile("cp.async.cg.shared.global [%0], [%1], 16;" :: "r"(d), "l"(g));
}
__device__ __forceinline__ void ldsm4(uint32_t (&r)[4], uint32_t addr) {
    asm volatile("ldmatrix.sync.aligned.m8n8.x4.shared.b16 {%0,%1,%2,%3}, [%4];"
        : "=r"(r[0]), "=r"(r[1]), "=r"(r[2]), "=r"(r[3]) : "r"(addr));
}
__device__ __forceinline__ void ldsm4t(uint32_t (&r)[4], uint32_t addr) {
    asm volatile("ldmatrix.sync.aligned.m8n8.x4.trans.shared.b16 {%0,%1,%2,%3}, [%4];"
        : "=r"(r[0]), "=r"(r[1]), "=r"(r[2]), "=r"(r[3]) : "r"(addr));
}
__device__ __forceinline__ void mma16816(float (&d)[4], const uint32_t (&a)[4],
                                         uint32_t b0, uint32_t b1) {
    asm volatile("mma.sync.aligned.m16n8k16.row.col.f32.f16.f16.f32 "
        "{%0,%1,%2,%3},{%4,%5,%6,%7},{%8,%9},{%0,%1,%2,%3};"
        : "+f"(d[0]), "+f"(d[1]), "+f"(d[2]), "+f"(d[3])
        : "r"(a[0]), "r"(a[1]), "r"(a[2]), "r"(a[3]), "r"(b0), "r"(b1));
}
__device__ __forceinline__ uint32_t pack2(float x0, float x1) {
    __half2 h = __floats2half2_rn(x0, x1);
    return *(uint32_t*)&h;
}
__device__ __forceinline__ float qmax(float v) {
    v = fmaxf(v, __shfl_xor_sync(0xffffffffu, v, 1));
    v = fmaxf(v, __shfl_xor_sync(0xffffffffu, v, 2));
    return v;
}
__device__ __forceinline__ float qsum(float v) {
    v += __shfl_xor_sync(0xffffffffu, v, 1);
    v += __shfl_xor_sync(0xffffffffu, v, 2);
    return v;
}

// ---------------------------------------------------------------------------
__global__ void theta_init_kernel() {
    int j = threadIdx.x;
    if (j < 64) g_theta[j] = (float)pow(10000.0, -(double)j / 64.0);
}

// x f32 -> f16
__global__ void f2h_kernel(const float* __restrict__ src, __half* __restrict__ dst, int n4) {
    int i = blockIdx.x * blockDim.x + threadIdx.x;
    if (i < n4) {
        float4 v = ((const float4*)src)[i];
        uint32_t* d = (uint32_t*)dst + (size_t)i * 2;
        d[0] = pack2(v.x, v.y);
        d[1] = pack2(v.z, v.w);
    }
}

// all 4 weights f32 -> f16, one launch. grid.y selects matrix.
__global__ void w_f2h_kernel(const float* __restrict__ w0, const float* __restrict__ w1,
                             const float* __restrict__ w2, const float* __restrict__ w3) {
    int i = blockIdx.x * blockDim.x + threadIdx.x;
    if (i >= WN_/4) return;
    const float* srcs[4] = { w0, w1, w2, w3 };
    const float* src = srcs[blockIdx.y];
    float4 v = ((const float4*)src)[i];
    uint32_t* d = (uint32_t*)(g_Wh + (size_t)blockIdx.y * WN_) + (size_t)i * 2;
    d[0] = pack2(v.x, v.y);
    d[1] = pack2(v.z, v.w);
}

// ---------------------------------------------------------------------------
// GEMM core: C tile [128x128] = A[M,K]@W[N,K]^T + bias, plain f16 HMMA.
// BM=BN=128, BK=64, 256 thr (8 warps 2x4).
// 3-stage cp.async pipeline, ONE barrier per K-chunk.
// mode 0: ->g_Q fp32 head-major   mode 1: ->g_K fp32 head-major
// mode 2: ->g_Vh f16 head-major   mode 3: ->outF fp32 row-major
// ---------------------------------------------------------------------------
#define MAT_B  (128*144)        // bytes per matrix per stage (128 rows x 144B pitch)
#define STAGE_B (2*MAT_B)       // Ah, Wh
#define GEMM_SMEM (3*STAGE_B)   // 110592

__device__ __forceinline__ void gemm_load_stage(
    uint32_t sb, const __half* Ah, const __half* Bh,
    int m0, int n0, int k0, int tid)
{
    #pragma unroll
    for (int mat = 0; mat < 2; ++mat) {
        const __half* src = mat ? Bh : Ah;
        int rbase = mat ? n0 : m0;
        #pragma unroll
        for (int p = 0; p < 4; ++p) {
            int idx = tid + p * 256;
            int row = idx >> 3, c16 = idx & 7;
            const __half* g = src + (size_t)(rbase + row) * E_ + k0 + c16 * 8;
            cp16(sb + mat * MAT_B + row * 144 + c16 * 16, g);
        }
    }
    asm volatile("cp.async.commit_group;" ::: "memory");
}

__device__ __forceinline__ void gemm_core(
    const __half* __restrict__ Ah, const __half* __restrict__ Bh,
    const float* __restrict__ bias, float* __restrict__ outF,
    int mode, uint32_t sbase)
{
    const int tid = threadIdx.x;
    const int lane = tid & 31;
    const int wid = tid >> 5;
    const int wm = wid >> 2, wn = wid & 3;
    const int n0 = blockIdx.x * 128;
    const int m0 = blockIdx.y * 128;

    float acc[4][4][4] = {};

    // prologue: chunks 0,1 -> slots 0,1
    gemm_load_stage(sbase,           Ah, Bh, m0, n0, 0,  tid);
    gemm_load_stage(sbase + STAGE_B, Ah, Bh, m0, n0, 64, tid);

    int slot = 0;
    for (int i = 0; i < E_/64; ++i) {
        asm volatile("cp.async.wait_group 1;" ::: "memory");   // chunk i landed
        __syncthreads();   // also proves slot (i-1)%3 is no longer being read

        // prefetch chunk i+2 into slot (i+2)%3 == (i-1)%3
        if (i + 2 < E_/64) {
            int ps = slot - 1; if (ps < 0) ps += 3;
            gemm_load_stage(sbase + ps * STAGE_B, Ah, Bh, m0, n0, (i + 2) * 64, tid);
        } else {
            asm volatile("cp.async.commit_group;" ::: "memory");  // uniform group count
        }

        const uint32_t sb = sbase + slot * STAGE_B;
        #pragma unroll
        for (int k16 = 0; k16 < 4; ++k16) {
            uint32_t ah[4][4];
            #pragma unroll
            for (int mf = 0; mf < 4; ++mf) {
                uint32_t addr = sb + (wm*64 + mf*16 + (lane & 15)) * 144
                              + k16*32 + (lane >> 4) * 16;
                ldsm4(ah[mf], addr);
            }
            uint32_t bh[2][4];
            #pragma unroll
            for (int g = 0; g < 2; ++g) {
                uint32_t addr = sb + MAT_B
                              + (wn*32 + g*16 + (lane & 7) + ((lane >> 4) & 1) * 8) * 144
                              + k16*32 + ((lane >> 3) & 1) * 16;
                ldsm4(bh[g], addr);
            }
            #pragma unroll
            for (int mf = 0; mf < 4; ++mf)
                #pragma unroll
                for (int nf = 0; nf < 4; ++nf) {
                    int g = nf >> 1, h = (nf & 1) * 2;
                    mma16816(acc[mf][nf], ah[mf], bh[g][h], bh[g][h+1]);
                }
        }
        if (++slot == 3) slot = 0;
    }

    // epilogue
    #pragma unroll
    for (int nf = 0; nf < 4; ++nf) {
        int d = wn*32 + nf*8 + (lane & 3) * 2;          // 0..127 within tile
        int gcol = n0 + d;
        float b0 = bias[gcol], b1 = bias[gcol + 1];
        #pragma unroll
        for (int mf = 0; mf < 4; ++mf) {
            int row0 = m0 + wm*64 + mf*16 + (lane >> 2);
            #pragma unroll
            for (int half = 0; half < 2; ++half) {
                int row = row0 + half * 8;
                float v0 = acc[mf][nf][half*2 + 0] + b0;
                float v1 = acc[mf][nf][half*2 + 1] + b1;
                if (mode == 3) {
                    *(float2*)(outF + (size_t)row * E_ + gcol) = make_float2(v0, v1);
                } else {
                    int b = row >> 11, t = row & (T_ - 1), h = blockIdx.x;
                    size_t idx = (((size_t)(b*H_ + h)) * T_ + t) * D_ + d;
                    if (mode == 2) {
                        *(uint32_t*)&g_Vh[idx] = pack2(v0, v1);
                    } else {
                        float* dst = (mode == 0) ? g_Q : g_K;
                        *(float2*)(dst + idx) = make_float2(v0, v1);
                    }
                }
            }
        }
    }
}

// fused Q/K/V projections: grid (16, 32, 3), z selects target
__global__ __launch_bounds__(256) void qkv_gemm(
    const float* __restrict__ bq, const float* __restrict__ bk,
    const float* __restrict__ bv)
{
    extern __shared__ __align__(16) char dsmem[];
    const int mode = blockIdx.z;
    const float* bias = (mode == 0) ? bq : (mode == 1) ? bk : bv;
    gemm_core(g_Xh, g_Wh + (size_t)mode * WN_, bias, nullptr, mode, smem_u32(dsmem));
}

// output projection: grid (16, 32)
__global__ __launch_bounds__(256) void out_gemm(
    const float* __restrict__ bo, float* __restrict__ outF)
{
    extern __shared__ __align__(16) char dsmem[];
    gemm_core(g_Yh, g_Wh + 3*(size_t)WN_, bo, outF, 3, smem_u32(dsmem));
}

// ---------------------------------------------------------------------------
// RoPE + scale (Q only) -> f16.
// ---------------------------------------------------------------------------
__global__ void rope_kernel() {
    const int total = B_*H_*T_*(D_/2);
    int idx = blockIdx.x * blockDim.x + threadIdx.x;
    if (idx >= total) return;
    int row = idx >> 6;
    int j   = idx & 63;
    int t   = row & (T_ - 1);
    float ang = (float)(t + 1) * g_theta[j];
    float s, c;
    sincosf(ang, &s, &c);
    int isK = blockIdx.y;
    const float* src = isK ? g_K : g_Q;
    __half* dst = isK ? g_Kh : g_Qh;
    size_t base = (size_t)row * D_;
    float x0 = src[base + j];
    float x1 = src[base + j + 64];
    float r0 = x0*c - x1*s;
    float r1 = x1*c + x0*s;
    if (!isK) { r0 *= QSCALE; r1 *= QSCALE; }
    dst[base + j]      = __float2half_rn(r0);
    dst[base + j + 64] = __float2half_rn(r1);
}

// ---------------------------------------------------------------------------
// Flash attention, causal, 1-pass f16 HMMA, fp32 softmax.
// grid (T/64, B*H), 128 threads (4 warps). BQ=64 (16 rows/warp), BKV=64.
// cp.async overlap: V load hidden under S+softmax, next-K load hidden under PV.
// Heavy q-tiles mapped to low blockIdx (wave-1 start).
// ---------------------------------------------------------------------------
#define AT_ROW 136                       // halves per smem row (128 + 8 pad)
#define AT_ROWB (AT_ROW*2)               // bytes per smem row
#define AT_TILE (64*AT_ROW)              // halves per matrix
#define ATTN_SMEM (3*AT_TILE*2)          // Q, K, V = 52224 B

__device__ __forceinline__ void attn_cp_tile(uint32_t dst, const __half* src, int tid) {
    #pragma unroll
    for (int p = 0; p < 8; ++p) {
        int idx = tid + p * 128;
        int row = idx >> 4, c8 = idx & 15;
        cp16(dst + row * AT_ROWB + c8 * 16, src + (size_t)row * D_ + c8 * 8);
    }
}

__global__ __launch_bounds__(128) void attn_tc() {
    extern __shared__ __align__(16) __half asmem[];
    __half* sQ = asmem;
    __half* sK = asmem + AT_TILE;
    __half* sV = asmem + 2*AT_TILE;
    const uint32_t uQ = smem_u32(sQ);
    const uint32_t uK = smem_u32(sK);
    const uint32_t uV = smem_u32(sV);

    const int tid = threadIdx.x;
    const int lane = tid & 31;
    const int w = tid >> 5;
    const int q0 = (int)(gridDim.x - 1 - blockIdx.x) * 64;   // heavy tiles first
    const int bh = blockIdx.y;
    const __half* Qhp = g_Qh + (size_t)bh * T_ * D_;
    const __half* Khp = g_Kh + (size_t)bh * T_ * D_;
    const __half* Vhp = g_Vh + (size_t)bh * T_ * D_;

    // prologue: Q tile + K_0 tile (one group)
    attn_cp_tile(uQ, Qhp + (size_t)q0 * D_, tid);
    attn_cp_tile(uK, Khp, tid);
    asm volatile("cp.async.commit_group;" ::: "memory");

    float of[16][4] = {};
    float m0 = -1e30f, m1 = -1e30f, l0 = 0.f, l1 = 0.f;
    const int nblocks = q0/64 + 1;

    for (int it = 0; it < nblocks; ++it) {
        const int k0 = it * 64;
        const bool diag = (it == nblocks - 1);

        asm volatile("cp.async.wait_group 0;" ::: "memory");   // K_it (and Q) ready
        __syncthreads();                                       // sV free (prev PV done)

        // issue V_it load — hidden under S + softmax
        attn_cp_tile(uV, Vhp + (size_t)k0 * D_, tid);
        asm volatile("cp.async.commit_group;" ::: "memory");

        // ---- S = Q K^T ----
        float sf[8][4] = {};
        #pragma unroll
        for (int k16 = 0; k16 < 8; ++k16) {
            uint32_t aqh[4];
            uint32_t aaddr = (w*16 + (lane & 15)) * AT_ROWB + k16*32 + (lane >> 4) * 16;
            ldsm4(aqh, uQ + aaddr);
            #pragma unroll
            for (int g = 0; g < 4; ++g) {
                uint32_t kbh[4];
                uint32_t baddr = (g*16 + (lane & 7) + ((lane >> 4) & 1) * 8) * AT_ROWB
                               + k16*32 + ((lane >> 3) & 1) * 16;
                ldsm4(kbh, uK + baddr);
                mma16816(sf[2*g],   aqh, kbh[0], kbh[1]);
                mma16816(sf[2*g+1], aqh, kbh[2], kbh[3]);
            }
        }

        // ---- mask (diagonal block only) ----
        const int rg0 = q0 + w*16 + (lane >> 2);
        if (diag) {
            #pragma unroll
            for (int n = 0; n < 8; ++n) {
                int col = k0 + n*8 + (lane & 3) * 2;
                if (col     > rg0)     sf[n][0] = -1e30f;
                if (col + 1 > rg0)     sf[n][1] = -1e30f;
                if (col     > rg0 + 8) sf[n][2] = -1e30f;
                if (col + 1 > rg0 + 8) sf[n][3] = -1e30f;
            }
        }

        // ---- online softmax ----
        float mx0 = -1e30f, mx1 = -1e30f;
        #pragma unroll
        for (int n = 0; n < 8; ++n) {
            mx0 = fmaxf(mx0, fmaxf(sf[n][0], sf[n][1]));
            mx1 = fmaxf(mx1, fmaxf(sf[n][2], sf[n][3]));
        }
        mx0 = qmax(mx0); mx1 = qmax(mx1);
        float mn0 = fmaxf(m0, mx0), mn1 = fmaxf(m1, mx1);
        float a0 = __expf(m0 - mn0), a1 = __expf(m1 - mn1);
        m0 = mn0; m1 = mn1;

        uint32_t pa[4][4];
        float s0 = 0.f, s1 = 0.f;
        #pragma unroll
        for (int n = 0; n < 8; ++n) {
            float p0 = __expf(sf[n][0] - mn0);
            float p1 = __expf(sf[n][1] - mn0);
            float p2 = __expf(sf[n][2] - mn1);
            float p3 = __expf(sf[n][3] - mn1);
            s0 += p0 + p1; s1 += p2 + p3;
            int kt = n >> 1, o = (n & 1) * 2;
            pa[kt][o + 0] = pack2(p0, p1);
            pa[kt][o + 1] = pack2(p2, p3);
        }
        s0 = qsum(s0); s1 = qsum(s1);
        l0 = l0 * a0 + s0;
        l1 = l1 * a1 + s1;
        #pragma unroll
        for (int n = 0; n < 16; ++n) {
            of[n][0] *= a0; of[n][1] *= a0;
            of[n][2] *= a1; of[n][3] *= a1;
        }

        asm volatile("cp.async.wait_group 0;" ::: "memory");   // V_it ready
        __syncthreads();                                       // sK free (all past S)

        // issue K_{it+1} load — hidden under PV
        if (it + 1 < nblocks) {
            attn_cp_tile(uK, Khp + (size_t)(k0 + 64) * D_, tid);
            asm volatile("cp.async.commit_group;" ::: "memory");
        }

        // ---- O += P V ----
        #pragma unroll
        for (int kt = 0; kt < 4; ++kt) {
            #pragma unroll
            for (int g = 0; g < 8; ++g) {
                uint32_t vbh[4];
                uint32_t vaddr = (kt*16 + (lane & 7) + ((lane >> 3) & 1) * 8) * AT_ROWB
                               + g*32 + ((lane >> 4) & 1) * 16;
                ldsm4t(vbh, uV + vaddr);
                mma16816(of[2*g],   pa[kt], vbh[0], vbh[1]);
                mma16816(of[2*g+1], pa[kt], vbh[2], vbh[3]);
            }
        }
    }

    // ---- epilogue: normalize, store f16 ----
    float inv0 = 1.0f / l0, inv1 = 1.0f / l1;
    const int b = bh >> 4, h = bh & 15;
    const int row0 = q0 + w*16 + (lane >> 2);
    size_t base0 = ((size_t)(b*T_ + row0)) * E_ + h*D_;
    size_t base1 = base0 + 8 * E_;
    #pragma unroll
    for (int n = 0; n < 16; ++n) {
        int col = n*8 + (lane & 3) * 2;
        *(uint32_t*)&g_Yh[base0 + col] = pack2(of[n][0] * inv0, of[n][1] * inv0);
        *(uint32_t*)&g_Yh[base1 + col] = pack2(of[n][2] * inv1, of[n][3] * inv1);
    }
}

// ---------------------------------------------------------------------------
extern "C" void kernel_launch(void* const* d_in, const int* in_sizes, int n_in,
                              void* d_out, int out_size) {
    const float* x  = (const float*)d_in[0];
    const float* Wq = (const float*)d_in[1];
    const float* bq = (const float*)d_in[2];
    const float* Wk = (const float*)d_in[3];
    const float* bk = (const float*)d_in[4];
    const float* Wv = (const float*)d_in[5];
    const float* bv = (const float*)d_in[6];
    const float* Wo = (const float*)d_in[7];
    const float* bo = (const float*)d_in[8];
    float* out = (float*)d_out;

    cudaFuncSetAttribute(qkv_gemm, cudaFuncAttributeMaxDynamicSharedMemorySize, GEMM_SMEM);
    cudaFuncSetAttribute(out_gemm, cudaFuncAttributeMaxDynamicSharedMemorySize, GEMM_SMEM);
    cudaFuncSetAttribute(attn_tc,  cudaFuncAttributeMaxDynamicSharedMemorySize, ATTN_SMEM);

    theta_init_kernel<<<1, 64>>>();

    __half* Xh;
    cudaGetSymbolAddress((void**)&Xh, g_Xh);

    f2h_kernel<<<(M_*E_/4 + 255)/256, 256>>>(x, Xh, M_*E_/4);
    dim3 gw((WN_/4 + 255)/256, 4);
    w_f2h_kernel<<<gw, 256>>>(Wq, Wk, Wv, Wo);

    dim3 gq(E_/128, M_/128, 3);
    qkv_gemm<<<gq, 256, GEMM_SMEM>>>(bq, bk, bv);

    const int rope_total = B_*H_*T_*(D_/2);
    dim3 g2((rope_total + 255)/256, 2);
    rope_kernel<<<g2, 256>>>();

    dim3 g3(T_/64, B_*H_);
    attn_tc<<<g3, 128, ATTN_SMEM>>>();

    dim3 go(E_/128, M_/128);
    out_gemm<<<go, 256, GEMM_SMEM>>>(bo, out);
}